// round 9
// baseline (speedup 1.0000x reference)
#include <cuda_runtime.h>
#include <cuda_fp16.h>
#include <cstdint>

// Problem constants (ClassicMambaBlock: B=2, L=2048, Dm=1024, E=2048, N=16, R=64, K=3)
static constexpr int BSZ  = 2;
static constexpr int LEN  = 2048;
static constexpr int DM   = 1024;
static constexpr int EE   = 2048;
static constexpr int NN   = 16;
static constexpr int RR   = 64;
static constexpr int SEL  = RR + 2 * NN;   // 96
static constexpr int SELP = 128;           // padded N for sel-GEMM tiling
static constexpr int MTOT = BSZ * LEN;     // 4096

// ---------------- scratch (no cudaMalloc allowed) ----------------
__device__ float  g_xz[MTOT * 2 * EE];     // [M,4096]: cols [0,E)=xc, [E,2E)=z
__device__ float2 g_ug[MTOT * EE];         // {u, silu(z)} per (t,e)
__device__ float  g_delta[MTOT * EE];      // softplus(dt)
__device__ float  g_dbc[MTOT * SEL];       // [M,96]: dt_low | B | C
// fp16 GEMM operands
__device__ __half g_xh[MTOT * DM];
__device__ __half g_winh[2 * EE * DM];
__device__ __half g_wselh[SELP * EE];      // rows 96..127 zero-padded
__device__ __half g_dtwh[EE * RR];
__device__ __half g_wouth[DM * EE];
__device__ __half g_uh[MTOT * EE];         // conv output (sel-GEMM A)
__device__ __half g_dtlh[MTOT * RR];       // dt_low (delta-GEMM A)
__device__ __half g_yh[MTOT * EE];         // scan output (out-GEMM A)

// ================= helpers =================
__device__ __forceinline__ uint32_t smem_u32(const void* p) {
    uint32_t a;
    asm("{ .reg .u64 t; cvta.to.shared.u64 t, %1; cvt.u32.u64 %0, t; }" : "=r"(a) : "l"(p));
    return a;
}
__device__ __forceinline__ void cp_async16(uint32_t dst, const void* src) {
    asm volatile("cp.async.cg.shared.global [%0], [%1], 16;" :: "r"(dst), "l"(src));
}
__device__ __forceinline__ void ldm_x4(uint32_t* r, uint32_t addr) {
    asm volatile("ldmatrix.sync.aligned.m8n8.x4.shared.b16 {%0,%1,%2,%3}, [%4];"
                 : "=r"(r[0]), "=r"(r[1]), "=r"(r[2]), "=r"(r[3]) : "r"(addr));
}
__device__ __forceinline__ void mma_f16(float* d, const uint32_t* a, const uint32_t* b) {
    asm volatile(
        "mma.sync.aligned.m16n8k16.row.col.f32.f16.f16.f32 "
        "{%0,%1,%2,%3}, {%4,%5,%6,%7}, {%8,%9}, {%0,%1,%2,%3};"
        : "+f"(d[0]), "+f"(d[1]), "+f"(d[2]), "+f"(d[3])
        : "r"(a[0]), "r"(a[1]), "r"(a[2]), "r"(a[3]), "r"(b[0]), "r"(b[1]));
}

// ---------------- fp32 -> fp16 convert pass (x + all weights) ----------------
static constexpr int C4_X    = MTOT * DM / 4;
static constexpr int C4_WIN  = 2 * EE * DM / 4;
static constexpr int C4_WSEL = SEL * EE / 4;
static constexpr int C4_DTW  = EE * RR / 4;
static constexpr int C4_WOUT = DM * EE / 4;
static constexpr int C4_PAD  = (SELP - SEL) * EE / 4;
static constexpr int C4_TOT  = C4_X + C4_WIN + C4_WSEL + C4_DTW + C4_WOUT + C4_PAD;

__global__ __launch_bounds__(256)
void to_half_kernel(const float4* __restrict__ x,    __half* __restrict__ xh,
                    const float4* __restrict__ win,  __half* __restrict__ winh,
                    const float4* __restrict__ wsel, __half* __restrict__ wselh,
                    const float4* __restrict__ dtw,  __half* __restrict__ dtwh,
                    const float4* __restrict__ wout, __half* __restrict__ wouth)
{
    int i = blockIdx.x * blockDim.x + threadIdx.x;
    if (i >= C4_TOT) return;
    const float4* src; __half* dst; int j = i;
    if (j < C4_X) { src = x; dst = xh; }
    else if ((j -= C4_X) < C4_WIN) { src = win; dst = winh; }
    else if ((j -= C4_WIN) < C4_WSEL) { src = wsel; dst = wselh; }
    else if ((j -= C4_WSEL) < C4_DTW) { src = dtw; dst = dtwh; }
    else if ((j -= C4_DTW) < C4_WOUT) { src = wout; dst = wouth; }
    else {  // zero pad rows 96..127 of wselh
        j -= C4_WOUT;
        reinterpret_cast<uint2*>(wselh + SEL * EE)[j] = make_uint2(0u, 0u);
        return;
    }
    float4 v = src[j];
    __half2 h01 = __floats2half2_rn(v.x, v.y);
    __half2 h23 = __floats2half2_rn(v.z, v.w);
    uint2 pk = make_uint2(*reinterpret_cast<uint32_t*>(&h01), *reinterpret_cast<uint32_t*>(&h23));
    reinterpret_cast<uint2*>(dst)[j] = pk;
}

// ================= fp16 tensor GEMM: C[M,N] = A[M,K] @ B[N,K]^T, fp32 accum =============
// BK = 64 fp16 (128B rows). smem: 16B unit at (c*ROWS + (r ^ c))*16, c = k/8.
// Loads issued before compute; single barrier per chunk; ldmatrix fragments.
// EPI: 0 = none; 1 = softplus(x+bias); 2 = dual write (fp32 cols<SEL into C with
// ldc, fp16 cols<RR into Ch with lda RR).
template<int BM, int BN, int WM, int WN, int STAGES, int EPI>
__global__ __launch_bounds__((BM / WM) * (BN / WN) * 32)
void mma_gemm(const __half* __restrict__ A, const __half* __restrict__ Bw,
              float* __restrict__ C, int K, int lda, int ldb, int ldc,
              const float* __restrict__ bias, __half* __restrict__ Ch)
{
    constexpr int WARPS_M = BM / WM;
    constexpr int WARPS_N = BN / WN;
    constexpr int THREADS = WARPS_M * WARPS_N * 32;
    constexpr int MT = WM / 16;
    constexpr int NT = WN / 8;
    constexpr int STAGE_B = (BM + BN) * 128;
    static_assert(NT % 2 == 0, "NT even");

    extern __shared__ char smem[];
    const uint32_t smem_b = smem_u32(smem);

    const int tid  = threadIdx.x;
    const int lane = tid & 31, wid = tid >> 5;
    const int wm = wid % WARPS_M, wn = wid / WARPS_M;
    const int qr = lane >> 2, kin = lane & 3;
    const int m0 = blockIdx.y * BM, n0 = blockIdx.x * BN;
    const int lrow = lane & 15, lcof = lane >> 4;

    float acc[MT][NT][4];
#pragma unroll
    for (int i = 0; i < MT; i++)
#pragma unroll
        for (int j = 0; j < NT; j++)
#pragma unroll
            for (int q = 0; q < 4; q++) acc[i][j][q] = 0.f;

    auto load_chunk = [&](int ck, int slot) {
        const int kt = ck * 64;
        const uint32_t ab = smem_b + slot * STAGE_B;
        const uint32_t bb = ab + BM * 128;
#pragma unroll
        for (int it = 0; it < BM * 8 / THREADS; it++) {
            int idx = tid + it * THREADS;
            int r = idx >> 3, c = idx & 7;
            cp_async16(ab + (uint32_t)(c * BM + (r ^ c)) * 16,
                       A + (size_t)(m0 + r) * lda + kt + c * 8);
        }
#pragma unroll
        for (int it = 0; it < BN * 8 / THREADS; it++) {
            int idx = tid + it * THREADS;
            int r = idx >> 3, c = idx & 7;
            cp_async16(bb + (uint32_t)(c * BN + (r ^ c)) * 16,
                       Bw + (size_t)(n0 + r) * ldb + kt + c * 8);
        }
        asm volatile("cp.async.commit_group;" ::: "memory");
    };

    const int nch = K / 64;
#pragma unroll
    for (int s = 0; s < STAGES - 1; s++)
        if (s < nch) load_chunk(s, s);

    for (int i = 0; i < nch; i++) {
        int w = nch - 1 - i;
        if (w > STAGES - 2) w = STAGES - 2;
        if      (w <= 0) asm volatile("cp.async.wait_group 0;" ::: "memory");
        else if (w == 1) asm volatile("cp.async.wait_group 1;" ::: "memory");
        else if (w == 2) asm volatile("cp.async.wait_group 2;" ::: "memory");
        else             asm volatile("cp.async.wait_group 3;" ::: "memory");
        __syncthreads();

        const int pre = i + STAGES - 1;
        if (pre < nch) load_chunk(pre, pre % STAGES);

        const uint32_t sa = smem_b + (i % STAGES) * STAGE_B;
        const uint32_t sb = sa + BM * 128;
#pragma unroll
        for (int ks = 0; ks < 4; ks++) {
            const int c = 2 * ks + lcof;
            uint32_t af[MT][4], bf[NT][2];
#pragma unroll
            for (int t = 0; t < MT; t++) {
                const int row = wm * WM + t * 16 + lrow;
                ldm_x4(af[t], sa + (uint32_t)(c * BM + (row ^ c)) * 16);
            }
#pragma unroll
            for (int p = 0; p < NT / 2; p++) {
                const int row = wn * WN + p * 16 + lrow;
                uint32_t r4[4];
                ldm_x4(r4, sb + (uint32_t)(c * BN + (row ^ c)) * 16);
                bf[2 * p][0] = r4[0]; bf[2 * p + 1][0] = r4[1];
                bf[2 * p][1] = r4[2]; bf[2 * p + 1][1] = r4[3];
            }
#pragma unroll
            for (int t = 0; t < MT; t++)
#pragma unroll
                for (int j = 0; j < NT; j++)
                    mma_f16(acc[t][j], af[t], bf[j]);
        }
        __syncthreads();
    }

    // ---------------- epilogue ----------------
#pragma unroll
    for (int t = 0; t < MT; t++) {
#pragma unroll
        for (int j = 0; j < NT; j++) {
            const int row = m0 + wm * WM + t * 16 + qr;
            const int col = n0 + wn * WN + j * 8 + kin * 2;
            float v0 = acc[t][j][0], v1 = acc[t][j][1];
            float v2 = acc[t][j][2], v3 = acc[t][j][3];
            if (EPI == 1) {
                const float b0 = bias[col], b1 = bias[col + 1];
                float x0 = v0 + b0, x1 = v1 + b1, x2 = v2 + b0, x3 = v3 + b1;
                v0 = (x0 > 20.f) ? x0 : log1pf(__expf(x0));
                v1 = (x1 > 20.f) ? x1 : log1pf(__expf(x1));
                v2 = (x2 > 20.f) ? x2 : log1pf(__expf(x2));
                v3 = (x3 > 20.f) ? x3 : log1pf(__expf(x3));
            }
            if (EPI == 2) {
                if (col < SEL) {
                    *reinterpret_cast<float2*>(C + (size_t)row * ldc + col)       = make_float2(v0, v1);
                    *reinterpret_cast<float2*>(C + (size_t)(row + 8) * ldc + col) = make_float2(v2, v3);
                }
                if (col < RR) {
                    *reinterpret_cast<__half2*>(Ch + (size_t)row * RR + col)
                        = __floats2half2_rn(v0, v1);
                    *reinterpret_cast<__half2*>(Ch + (size_t)(row + 8) * RR + col)
                        = __floats2half2_rn(v2, v3);
                }
            } else {
                *reinterpret_cast<float2*>(C + (size_t)row * ldc + col)       = make_float2(v0, v1);
                *reinterpret_cast<float2*>(C + (size_t)(row + 8) * ldc + col) = make_float2(v2, v3);
            }
        }
    }
}

// ---------------- causal depthwise conv1d (K=3) + bias + SiLU; also silu(z) -------------
// Per-batch: xz_b is this batch's [LEN, 2E] slice.
__global__ __launch_bounds__(256)
void conv_silu_kernel(const float* __restrict__ xz_b,
                      const float* __restrict__ cw,
                      const float* __restrict__ cb,
                      float2* __restrict__ ug_b,
                      __half* __restrict__ uh_b)
{
    int idx = blockIdx.x * blockDim.x + threadIdx.x;   // over LEN*E
    int e = idx % EE;
    int t = idx / EE;

    float acc = cb[e];
    float w0 = cw[e * 3 + 0], w1 = cw[e * 3 + 1], w2 = cw[e * 3 + 2];
    if (t >= 2) acc = fmaf(w0, xz_b[(size_t)(t - 2) * (2 * EE) + e], acc);
    if (t >= 1) acc = fmaf(w1, xz_b[(size_t)(t - 1) * (2 * EE) + e], acc);
    acc = fmaf(w2, xz_b[(size_t)t * (2 * EE) + e], acc);
    float s = acc / (1.f + __expf(-acc));                  // silu(conv)
    float zv = xz_b[(size_t)t * (2 * EE) + EE + e];        // z
    float gz = zv / (1.f + __expf(-zv));                   // silu(z)
    ug_b[idx] = make_float2(s, gz);
    uh_b[idx] = __float2half_rn(s);
}

// ---------------- selective scan (per batch): {u,gz} + packed B/C + delta ----------------
__global__ __launch_bounds__(256)
void scan_kernel(const float* __restrict__ delta_b,
                 const float2* __restrict__ ug_b,
                 const float* __restrict__ dbc_b,
                 const float* __restrict__ A_log,
                 const float* __restrict__ D_param,
                 __half* __restrict__ yh_b)
{
    const int e    = blockIdx.x * (blockDim.x >> 4) + (threadIdx.x >> 4); // [0, E)
    const int lane = threadIdx.x & 31;
    const int n    = threadIdx.x & 15;

    const float An = -__expf(A_log[e * NN + n]);
    const float Dp = D_param[e];

    const float*  dptr = delta_b + e;
    const float2* gptr = ug_b + e;
    const float*  vptr = dbc_b + RR + lane;   // lanes 0-15: B[n], 16-31: C[n]
    __half*       yptr = yh_b + e;

    float h = 0.f;
    float  d0 = dptr[0], d1 = dptr[EE];
    float2 g0 = gptr[0], g1 = gptr[EE];
    float  v0 = vptr[0], v1 = vptr[SEL];

    for (int t = 0; t < LEN; t++) {
        float d2 = 0.f, v2 = 0.f;
        float2 g2 = make_float2(0.f, 0.f);
        if (t + 2 < LEN) {
            d2 = dptr[(size_t)(t + 2) * EE];
            g2 = gptr[(size_t)(t + 2) * EE];
            v2 = vptr[(size_t)(t + 2) * SEL];
        }
        const float Bc = __shfl_sync(0xffffffffu, v0, n);        // B_t[n] (same for all e)
        const float Cc = __shfl_sync(0xffffffffu, v0, n + 16);   // C_t[n]
        float dA = __expf(d0 * An);
        h = fmaf(dA, h, d0 * g0.x * Bc);
        float p = h * Cc;
        p += __shfl_xor_sync(0xffffffffu, p, 1);
        p += __shfl_xor_sync(0xffffffffu, p, 2);
        p += __shfl_xor_sync(0xffffffffu, p, 4);
        p += __shfl_xor_sync(0xffffffffu, p, 8);
        if (n == 0)
            yptr[(size_t)t * EE] = __float2half_rn((p + g0.x * Dp) * g0.y);
        d0 = d1; g0 = g1; v0 = v1;
        d1 = d2; g1 = g2; v1 = v2;
    }
}

// ---------------- launch: two concurrent per-batch chains ----------------
extern "C" void kernel_launch(void* const* d_in, const int* in_sizes, int n_in,
                              void* d_out, int out_size)
{
    const float* x       = (const float*)d_in[0];
    const float* W_in    = (const float*)d_in[1];
    const float* conv_w  = (const float*)d_in[2];
    const float* conv_b  = (const float*)d_in[3];
    const float* W_sel   = (const float*)d_in[4];
    const float* dt_w    = (const float*)d_in[5];
    const float* dt_b    = (const float*)d_in[6];
    const float* A_log   = (const float*)d_in[7];
    const float* D_param = (const float*)d_in[8];
    const float* W_out   = (const float*)d_in[9];
    float* out = (float*)d_out;

    float *xz, *delta, *dbc;
    float2* ug;
    __half *xh, *winh, *wselh, *dtwh, *wouth, *uh, *dtlh, *yh;
    cudaGetSymbolAddress((void**)&xz,    g_xz);
    cudaGetSymbolAddress((void**)&ug,    g_ug);
    cudaGetSymbolAddress((void**)&delta, g_delta);
    cudaGetSymbolAddress((void**)&dbc,   g_dbc);
    cudaGetSymbolAddress((void**)&xh,    g_xh);
    cudaGetSymbolAddress((void**)&winh,  g_winh);
    cudaGetSymbolAddress((void**)&wselh, g_wselh);
    cudaGetSymbolAddress((void**)&dtwh,  g_dtwh);
    cudaGetSymbolAddress((void**)&wouth, g_wouth);
    cudaGetSymbolAddress((void**)&uh,    g_uh);
    cudaGetSymbolAddress((void**)&dtlh,  g_dtlh);
    cudaGetSymbolAddress((void**)&yh,    g_yh);

    auto* k_big = mma_gemm<128,  64, 32, 32, 4, 0>;
    auto* k_dlt = mma_gemm<128,  64, 32, 32, 2, 1>;
    auto* k_sel = mma_gemm< 32, 128, 32, 16, 4, 2>;

    constexpr int SM_BIG = 4 * (128 +  64) * 128;  // 98304
    constexpr int SM_DLT = 2 * (128 +  64) * 128;  // 49152
    constexpr int SM_SEL = 4 * ( 32 + 128) * 128;  // 81920
    cudaFuncSetAttribute((const void*)k_big, cudaFuncAttributeMaxDynamicSharedMemorySize, SM_BIG);
    cudaFuncSetAttribute((const void*)k_dlt, cudaFuncAttributeMaxDynamicSharedMemorySize, SM_DLT);
    cudaFuncSetAttribute((const void*)k_sel, cudaFuncAttributeMaxDynamicSharedMemorySize, SM_SEL);

    // Fork/join plumbing (host objects only; created per call, never freed —
    // destroying them mid-capture would invalidate the graph).
    cudaStream_t s1;
    cudaStreamCreateWithFlags(&s1, cudaStreamNonBlocking);
    cudaEvent_t evFork, evJoin;
    cudaEventCreateWithFlags(&evFork, cudaEventDisableTiming);
    cudaEventCreateWithFlags(&evJoin, cudaEventDisableTiming);

    // 0) convert x + weights to fp16 (shared by both chains)
    to_half_kernel<<<(C4_TOT + 255) / 256, 256>>>(
        (const float4*)x, xh, (const float4*)W_in, winh,
        (const float4*)W_sel, wselh, (const float4*)dt_w, dtwh,
        (const float4*)W_out, wouth);

    cudaEventRecord(evFork, 0);
    cudaStreamWaitEvent(s1, evFork, 0);

    for (int b = 0; b < BSZ; b++) {
        cudaStream_t st = (b == 0) ? (cudaStream_t)0 : s1;
        const size_t mo = (size_t)b * LEN;   // row offset

        // 1) xz_b = x_b @ W_in^T   [2048, 4096], K=1024
        k_big<<<dim3((2 * EE) / 64, LEN / 128), 256, SM_BIG, st>>>(
            xh + mo * DM, winh, xz + mo * 2 * EE, DM, DM, DM, 2 * EE, nullptr, nullptr);

        // 2) conv + silu + silu(z)
        conv_silu_kernel<<<(LEN * EE) / 256, 256, 0, st>>>(
            xz + mo * 2 * EE, conv_w, conv_b,
            ug + mo * EE, uh + mo * EE);

        // 3) dbc_b = u_b @ W_sel^T  [2048, 96(pad128)], K=2048 (+ fp16 dt_low)
        k_sel<<<dim3(1, LEN / 32), 256, SM_SEL, st>>>(
            uh + mo * EE, wselh, dbc + mo * SEL, EE, EE, EE, SEL, nullptr,
            dtlh + mo * RR);

        // 4) delta_b = softplus(dt_low_b @ dt_w^T + dt_b)  [2048, 2048], K=64
        k_dlt<<<dim3(EE / 64, LEN / 128), 256, SM_DLT, st>>>(
            dtlh + mo * RR, dtwh, delta + mo * EE, RR, RR, RR, EE, dt_b, nullptr);

        // 5) selective scan -> y_b (fp16)
        scan_kernel<<<EE / 16, 256, 0, st>>>(
            delta + mo * EE, ug + mo * EE, dbc + mo * SEL,
            A_log, D_param, yh + mo * EE);

        // 6) out_b = y_b @ W_out^T  [2048, 1024], K=2048
        k_big<<<dim3(DM / 64, LEN / 128), 256, SM_BIG, st>>>(
            yh + mo * EE, wouth, out + mo * DM, EE, EE, EE, DM, nullptr, nullptr);
    }

    cudaEventRecord(evJoin, s1);
    cudaStreamWaitEvent(0, evJoin, 0);
}

// round 10
// speedup vs baseline: 1.1197x; 1.1197x over previous
#include <cuda_runtime.h>
#include <cuda_fp16.h>
#include <cstdint>

// Problem constants (ClassicMambaBlock: B=2, L=2048, Dm=1024, E=2048, N=16, R=64, K=3)
static constexpr int BSZ  = 2;
static constexpr int LEN  = 2048;
static constexpr int DM   = 1024;
static constexpr int EE   = 2048;
static constexpr int NN   = 16;
static constexpr int RR   = 64;
static constexpr int SEL  = RR + 2 * NN;   // 96
static constexpr int SELP = 128;           // padded to 128 for GEMM3 tiling
static constexpr int MTOT = BSZ * LEN;     // 4096

// ---------------- scratch (no cudaMalloc allowed; +2 rows padding for scan prefetch) ----
__device__ float  g_xz[MTOT * 2 * EE];        // [M,4096]: cols [0,E)=xc, [E,2E)=z
__device__ float2 g_ug[(MTOT + 2) * EE];      // {u, silu(z)} per (t,e)
__device__ float  g_delta[(MTOT + 2) * EE];   // softplus(dt)
__device__ float  g_dbc[(MTOT + 2) * SEL];    // [M,96]: dt_low | B | C
// fp16 GEMM operands
__device__ __half g_xh[MTOT * DM];
__device__ __half g_winh[2 * EE * DM];
__device__ __half g_wselh[SELP * EE];         // rows 96..127 zero-padded
__device__ __half g_dtwh[EE * RR];
__device__ __half g_wouth[DM * EE];
__device__ __half g_uh[MTOT * EE];            // conv output (sel-GEMM A)
__device__ __half g_dtlh[MTOT * RR];          // dt_low (delta-GEMM A), lda=64
__device__ __half g_yh[MTOT * EE];            // scan output (out-GEMM A)

// ================= helpers =================
__device__ __forceinline__ uint32_t smem_u32(const void* p) {
    uint32_t a;
    asm("{ .reg .u64 t; cvta.to.shared.u64 t, %1; cvt.u32.u64 %0, t; }" : "=r"(a) : "l"(p));
    return a;
}
__device__ __forceinline__ void cp_async16(uint32_t dst, const void* src) {
    asm volatile("cp.async.cg.shared.global [%0], [%1], 16;" :: "r"(dst), "l"(src));
}
__device__ __forceinline__ void ldm_x4(uint32_t* r, uint32_t addr) {
    asm volatile("ldmatrix.sync.aligned.m8n8.x4.shared.b16 {%0,%1,%2,%3}, [%4];"
                 : "=r"(r[0]), "=r"(r[1]), "=r"(r[2]), "=r"(r[3]) : "r"(addr));
}
__device__ __forceinline__ void mma_f16(float* d, const uint32_t* a, const uint32_t* b) {
    asm volatile(
        "mma.sync.aligned.m16n8k16.row.col.f32.f16.f16.f32 "
        "{%0,%1,%2,%3}, {%4,%5,%6,%7}, {%8,%9}, {%0,%1,%2,%3};"
        : "+f"(d[0]), "+f"(d[1]), "+f"(d[2]), "+f"(d[3])
        : "r"(a[0]), "r"(a[1]), "r"(a[2]), "r"(a[3]), "r"(b[0]), "r"(b[1]));
}

// ---------------- fp32 -> fp16 convert pass (x + all weights) ----------------
static constexpr int C4_X    = MTOT * DM / 4;
static constexpr int C4_WIN  = 2 * EE * DM / 4;
static constexpr int C4_WSEL = SEL * EE / 4;
static constexpr int C4_DTW  = EE * RR / 4;
static constexpr int C4_WOUT = DM * EE / 4;
static constexpr int C4_PAD  = (SELP - SEL) * EE / 4;
static constexpr int C4_TOT  = C4_X + C4_WIN + C4_WSEL + C4_DTW + C4_WOUT + C4_PAD;

__global__ __launch_bounds__(256)
void to_half_kernel(const float4* __restrict__ x,    __half* __restrict__ xh,
                    const float4* __restrict__ win,  __half* __restrict__ winh,
                    const float4* __restrict__ wsel, __half* __restrict__ wselh,
                    const float4* __restrict__ dtw,  __half* __restrict__ dtwh,
                    const float4* __restrict__ wout, __half* __restrict__ wouth)
{
    int i = blockIdx.x * blockDim.x + threadIdx.x;
    if (i >= C4_TOT) return;
    const float4* src; __half* dst; int j = i;
    if (j < C4_X) { src = x; dst = xh; }
    else if ((j -= C4_X) < C4_WIN) { src = win; dst = winh; }
    else if ((j -= C4_WIN) < C4_WSEL) { src = wsel; dst = wselh; }
    else if ((j -= C4_WSEL) < C4_DTW) { src = dtw; dst = dtwh; }
    else if ((j -= C4_DTW) < C4_WOUT) { src = wout; dst = wouth; }
    else {  // zero pad rows 96..127 of wselh
        j -= C4_WOUT;
        reinterpret_cast<uint2*>(wselh + SEL * EE)[j] = make_uint2(0u, 0u);
        return;
    }
    float4 v = src[j];
    __half2 h01 = __floats2half2_rn(v.x, v.y);
    __half2 h23 = __floats2half2_rn(v.z, v.w);
    uint2 pk = make_uint2(*reinterpret_cast<uint32_t*>(&h01), *reinterpret_cast<uint32_t*>(&h23));
    reinterpret_cast<uint2*>(dst)[j] = pk;
}

// ================= fp16 tensor GEMM: C[M,N] = A[M,K] @ B[N,K]^T, fp32 accum =============
// Exact R6 mainloop (best measured). BK = 64 fp16 (128B rows). smem: 16B unit at
// (c*ROWS + (r ^ c))*16, c = k/8. ldmatrix.x4 fragments; STAGES-deep cp.async pipeline.
// EPI: 0 = none; 1 = softplus(x+bias); 2 = dual write (fp32 cols<SEL into C with ldc,
// fp16 cols<RR into Ch with lda RR).
template<int BM, int BN, int WM, int WN, int STAGES, int EPI>
__global__ __launch_bounds__((BM / WM) * (BN / WN) * 32)
void mma_gemm(const __half* __restrict__ A, const __half* __restrict__ Bw,
              float* __restrict__ C, int K, int lda, int ldb, int ldc,
              const float* __restrict__ bias, __half* __restrict__ Ch)
{
    constexpr int WARPS_M = BM / WM;
    constexpr int WARPS_N = BN / WN;
    constexpr int THREADS = WARPS_M * WARPS_N * 32;
    constexpr int MT = WM / 16;
    constexpr int NT = WN / 8;
    constexpr int STAGE_B = (BM + BN) * 128;
    static_assert(NT % 2 == 0, "NT even");

    extern __shared__ char smem[];
    const uint32_t smem_b = smem_u32(smem);

    const int tid  = threadIdx.x;
    const int lane = tid & 31, wid = tid >> 5;
    const int wm = wid % WARPS_M, wn = wid / WARPS_M;
    const int qr = lane >> 2, kin = lane & 3;
    const int m0 = blockIdx.y * BM, n0 = blockIdx.x * BN;
    const int lrow = lane & 15, lcof = lane >> 4;

    float acc[MT][NT][4];
#pragma unroll
    for (int i = 0; i < MT; i++)
#pragma unroll
        for (int j = 0; j < NT; j++)
#pragma unroll
            for (int q = 0; q < 4; q++) acc[i][j][q] = 0.f;

    auto load_chunk = [&](int ck, int slot) {
        const int kt = ck * 64;
        const uint32_t ab = smem_b + slot * STAGE_B;
        const uint32_t bb = ab + BM * 128;
#pragma unroll
        for (int it = 0; it < BM * 8 / THREADS; it++) {
            int idx = tid + it * THREADS;
            int r = idx >> 3, c = idx & 7;
            cp_async16(ab + (uint32_t)(c * BM + (r ^ c)) * 16,
                       A + (size_t)(m0 + r) * lda + kt + c * 8);
        }
#pragma unroll
        for (int it = 0; it < BN * 8 / THREADS; it++) {
            int idx = tid + it * THREADS;
            int r = idx >> 3, c = idx & 7;
            cp_async16(bb + (uint32_t)(c * BN + (r ^ c)) * 16,
                       Bw + (size_t)(n0 + r) * ldb + kt + c * 8);
        }
        asm volatile("cp.async.commit_group;" ::: "memory");
    };

    const int nch = K / 64;
#pragma unroll
    for (int s = 0; s < STAGES - 1; s++)
        if (s < nch) load_chunk(s, s);

    for (int i = 0; i < nch; i++) {
        int w = nch - 1 - i;
        if (w > STAGES - 2) w = STAGES - 2;
        if      (w <= 0) asm volatile("cp.async.wait_group 0;" ::: "memory");
        else if (w == 1) asm volatile("cp.async.wait_group 1;" ::: "memory");
        else if (w == 2) asm volatile("cp.async.wait_group 2;" ::: "memory");
        else if (w == 3) asm volatile("cp.async.wait_group 3;" ::: "memory");
        else             asm volatile("cp.async.wait_group 4;" ::: "memory");
        __syncthreads();

        const uint32_t sa = smem_b + (i % STAGES) * STAGE_B;
        const uint32_t sb = sa + BM * 128;
#pragma unroll
        for (int ks = 0; ks < 4; ks++) {
            const int c = 2 * ks + lcof;
            uint32_t af[MT][4], bf[NT][2];
#pragma unroll
            for (int t = 0; t < MT; t++) {
                const int row = wm * WM + t * 16 + lrow;
                ldm_x4(af[t], sa + (uint32_t)(c * BM + (row ^ c)) * 16);
            }
#pragma unroll
            for (int p = 0; p < NT / 2; p++) {
                const int row = wn * WN + p * 16 + lrow;
                uint32_t r4[4];
                ldm_x4(r4, sb + (uint32_t)(c * BN + (row ^ c)) * 16);
                bf[2 * p][0] = r4[0]; bf[2 * p + 1][0] = r4[1];
                bf[2 * p][1] = r4[2]; bf[2 * p + 1][1] = r4[3];
            }
#pragma unroll
            for (int t = 0; t < MT; t++)
#pragma unroll
                for (int j = 0; j < NT; j++)
                    mma_f16(acc[t][j], af[t], bf[j]);
        }
        __syncthreads();

        const int pre = i + STAGES - 1;
        if (pre < nch) load_chunk(pre, pre % STAGES);
    }

    // ---------------- epilogue ----------------
#pragma unroll
    for (int t = 0; t < MT; t++) {
#pragma unroll
        for (int j = 0; j < NT; j++) {
            const int row = m0 + wm * WM + t * 16 + qr;
            const int col = n0 + wn * WN + j * 8 + kin * 2;
            float v0 = acc[t][j][0], v1 = acc[t][j][1];
            float v2 = acc[t][j][2], v3 = acc[t][j][3];
            if (EPI == 1) {
                const float b0 = bias[col], b1 = bias[col + 1];
                float x0 = v0 + b0, x1 = v1 + b1, x2 = v2 + b0, x3 = v3 + b1;
                v0 = (x0 > 20.f) ? x0 : log1pf(__expf(x0));
                v1 = (x1 > 20.f) ? x1 : log1pf(__expf(x1));
                v2 = (x2 > 20.f) ? x2 : log1pf(__expf(x2));
                v3 = (x3 > 20.f) ? x3 : log1pf(__expf(x3));
            }
            if (EPI == 2) {
                if (col < SEL) {
                    *reinterpret_cast<float2*>(C + (size_t)row * ldc + col)       = make_float2(v0, v1);
                    *reinterpret_cast<float2*>(C + (size_t)(row + 8) * ldc + col) = make_float2(v2, v3);
                }
                if (col < RR) {
                    *reinterpret_cast<__half2*>(Ch + (size_t)row * RR + col)
                        = __floats2half2_rn(v0, v1);
                    *reinterpret_cast<__half2*>(Ch + (size_t)(row + 8) * RR + col)
                        = __floats2half2_rn(v2, v3);
                }
            } else {
                *reinterpret_cast<float2*>(C + (size_t)row * ldc + col)       = make_float2(v0, v1);
                *reinterpret_cast<float2*>(C + (size_t)(row + 8) * ldc + col) = make_float2(v2, v3);
            }
        }
    }
}

// ---------------- causal depthwise conv1d (K=3) + bias + SiLU; also silu(z) -------------
__global__ __launch_bounds__(256)
void conv_silu_kernel(const float* __restrict__ xz,
                      const float* __restrict__ cw,
                      const float* __restrict__ cb,
                      float2* __restrict__ ug,
                      __half* __restrict__ uh)
{
    int idx = blockIdx.x * blockDim.x + threadIdx.x;   // over B*L*E = 8.4M
    int e = idx % EE;
    int bt = idx / EE;
    int t = bt % LEN;
    const float* xc = xz + (size_t)(bt - t) * (2 * EE);

    float acc = cb[e];
    float w0 = cw[e * 3 + 0], w1 = cw[e * 3 + 1], w2 = cw[e * 3 + 2];
    if (t >= 2) acc = fmaf(w0, xc[(size_t)(t - 2) * (2 * EE) + e], acc);
    if (t >= 1) acc = fmaf(w1, xc[(size_t)(t - 1) * (2 * EE) + e], acc);
    acc = fmaf(w2, xc[(size_t)t * (2 * EE) + e], acc);
    float s = acc / (1.f + __expf(-acc));              // silu(conv)
    float zv = xc[(size_t)t * (2 * EE) + EE + e];      // z
    float gz = zv / (1.f + __expf(-zv));               // silu(z)
    ug[idx] = make_float2(s, gz);
    uh[idx] = __float2half_rn(s);
}

// ---------------- selective scan: 3 LDG/iter, no tail branch (padded arrays) ------------
__global__ __launch_bounds__(256)
void scan_kernel(const float* __restrict__ delta,
                 const float2* __restrict__ ug,
                 const float* __restrict__ dbc,
                 const float* __restrict__ A_log,
                 const float* __restrict__ D_param,
                 __half* __restrict__ yout)
{
    const int gid  = blockIdx.x * (blockDim.x >> 4) + (threadIdx.x >> 4); // channel b*E+e
    const int lane = threadIdx.x & 31;
    const int n    = threadIdx.x & 15;
    const int b    = gid / EE;
    const int e    = gid % EE;

    const float An = -__expf(A_log[e * NN + n]);
    const float Dp = D_param[e];

    const float*  dptr = delta + (size_t)b * LEN * EE + e;
    const float2* gptr = ug    + (size_t)b * LEN * EE + e;
    const float*  vptr = dbc   + (size_t)b * LEN * SEL + RR + lane;  // B|C packed, 1 LDG
    __half*       yptr = yout  + (size_t)b * LEN * EE + e;

    float h = 0.f;
    float  d0 = dptr[0], d1 = dptr[EE];
    float2 g0 = gptr[0], g1 = gptr[EE];
    float  v0 = vptr[0], v1 = vptr[SEL];

    for (int t = 0; t < LEN; t++) {
        // unconditional prefetch (arrays padded by 2 rows; tail values unused)
        float  d2 = dptr[(size_t)(t + 2) * EE];
        float2 g2 = gptr[(size_t)(t + 2) * EE];
        float  v2 = vptr[(size_t)(t + 2) * SEL];

        const float Bc = __shfl_sync(0xffffffffu, v0, n);        // B_t[n]
        const float Cc = __shfl_sync(0xffffffffu, v0, n + 16);   // C_t[n]
        float dA = __expf(d0 * An);
        h = fmaf(dA, h, d0 * g0.x * Bc);
        float p = h * Cc;
        p += __shfl_xor_sync(0xffffffffu, p, 1);
        p += __shfl_xor_sync(0xffffffffu, p, 2);
        p += __shfl_xor_sync(0xffffffffu, p, 4);
        p += __shfl_xor_sync(0xffffffffu, p, 8);
        if (n == 0)
            yptr[(size_t)t * EE] = __float2half_rn((p + g0.x * Dp) * g0.y);
        d0 = d1; g0 = g1; v0 = v1;
        d1 = d2; g1 = g2; v1 = v2;
    }
}

// ---------------- launch (single stream, R6 structure) ----------------
extern "C" void kernel_launch(void* const* d_in, const int* in_sizes, int n_in,
                              void* d_out, int out_size)
{
    const float* x       = (const float*)d_in[0];
    const float* W_in    = (const float*)d_in[1];
    const float* conv_w  = (const float*)d_in[2];
    const float* conv_b  = (const float*)d_in[3];
    const float* W_sel   = (const float*)d_in[4];
    const float* dt_w    = (const float*)d_in[5];
    const float* dt_b    = (const float*)d_in[6];
    const float* A_log   = (const float*)d_in[7];
    const float* D_param = (const float*)d_in[8];
    const float* W_out   = (const float*)d_in[9];
    float* out = (float*)d_out;

    float *xz, *delta, *dbc;
    float2* ug;
    __half *xh, *winh, *wselh, *dtwh, *wouth, *uh, *dtlh, *yh;
    cudaGetSymbolAddress((void**)&xz,    g_xz);
    cudaGetSymbolAddress((void**)&ug,    g_ug);
    cudaGetSymbolAddress((void**)&delta, g_delta);
    cudaGetSymbolAddress((void**)&dbc,   g_dbc);
    cudaGetSymbolAddress((void**)&xh,    g_xh);
    cudaGetSymbolAddress((void**)&winh,  g_winh);
    cudaGetSymbolAddress((void**)&wselh, g_wselh);
    cudaGetSymbolAddress((void**)&dtwh,  g_dtwh);
    cudaGetSymbolAddress((void**)&wouth, g_wouth);
    cudaGetSymbolAddress((void**)&uh,    g_uh);
    cudaGetSymbolAddress((void**)&dtlh,  g_dtlh);
    cudaGetSymbolAddress((void**)&yh,    g_yh);

    // R6 kernel variants (best measured)
    auto* k_big = mma_gemm<128, 128, 32, 32, 4, 0>;   // 512 thr, 16 warps, 4 stages
    auto* k_dlt = mma_gemm<128, 128, 32, 32, 2, 1>;   // 512 thr, K=64 -> 1 chunk
    auto* k_sel = mma_gemm< 32, 128, 32, 16, 6, 2>;   // 256 thr, 6 stages, dual-write

    constexpr int SM_BIG = 4 * (128 + 128) * 128;  // 131072
    constexpr int SM_DLT = 2 * (128 + 128) * 128;  // 65536
    constexpr int SM_SEL = 6 * ( 32 + 128) * 128;  // 122880
    cudaFuncSetAttribute((const void*)k_big, cudaFuncAttributeMaxDynamicSharedMemorySize, SM_BIG);
    cudaFuncSetAttribute((const void*)k_dlt, cudaFuncAttributeMaxDynamicSharedMemorySize, SM_DLT);
    cudaFuncSetAttribute((const void*)k_sel, cudaFuncAttributeMaxDynamicSharedMemorySize, SM_SEL);

    // 0) convert x + weights to fp16 (and zero-pad wselh)
    to_half_kernel<<<(C4_TOT + 255) / 256, 256>>>(
        (const float4*)x, xh, (const float4*)W_in, winh,
        (const float4*)W_sel, wselh, (const float4*)dt_w, dtwh,
        (const float4*)W_out, wouth);

    // 1) xz = x @ W_in^T   [4096, 4096], K=1024
    k_big<<<dim3((2 * EE) / 128, MTOT / 128), 512, SM_BIG>>>(
        xh, winh, xz, DM, DM, DM, 2 * EE, nullptr, nullptr);

    // 2) u = silu(causal_dwconv(xc) + b); silu(z) -> ug, uh fp16
    conv_silu_kernel<<<(MTOT * EE) / 256, 256>>>(xz, conv_w, conv_b, ug, uh);

    // 3) dbc = u @ W_sel^T   [4096, 96(pad128)], K=2048  (+ fp16 dt_low)
    k_sel<<<dim3(1, MTOT / 32), 256, SM_SEL>>>(
        uh, wselh, dbc, EE, EE, EE, SEL, nullptr, dtlh);

    // 4) delta = softplus(dt_low @ dt_w^T + dt_b)   [4096, 2048], K=64
    k_dlt<<<dim3(EE / 128, MTOT / 128), 512, SM_DLT>>>(
        dtlh, dtwh, delta, RR, RR, RR, EE, dt_b, nullptr);

    // 5) selective scan + D-skip + z-gating -> y (fp16)
    scan_kernel<<<(BSZ * EE) / 16, 256>>>(delta, ug, dbc, A_log, D_param, yh);

    // 6) out = y @ W_out^T   [4096, 1024], K=2048
    k_big<<<dim3(DM / 128, MTOT / 128), 512, SM_BIG>>>(
        yh, wouth, out, EE, EE, EE, DM, nullptr, nullptr);
}

// round 11
// speedup vs baseline: 1.1455x; 1.0231x over previous
#include <cuda_runtime.h>
#include <cuda_fp16.h>
#include <cstdint>

// Problem constants (ClassicMambaBlock: B=2, L=2048, Dm=1024, E=2048, N=16, R=64, K=3)
static constexpr int BSZ  = 2;
static constexpr int LEN  = 2048;
static constexpr int DM   = 1024;
static constexpr int EE   = 2048;
static constexpr int NN   = 16;
static constexpr int RR   = 64;
static constexpr int SEL  = RR + 2 * NN;   // 96
static constexpr int SELP = 128;           // padded to 128 for sel-GEMM tiling
static constexpr int MTOT = BSZ * LEN;     // 4096

// ---------------- scratch (no cudaMalloc allowed; +2 rows padding for scan prefetch) ----
__device__ float  g_xz[MTOT * 2 * EE];        // [M,4096]: cols [0,E)=xc, [E,2E)=z
__device__ float2 g_ug[(MTOT + 2) * EE];      // {u, silu(z)} per (t,e)
__device__ float  g_delta[(MTOT + 2) * EE];   // softplus(dt)
__device__ float  g_dbc[(MTOT + 2) * SEL];    // [M,96]: dt_low | B | C
// fp16 GEMM operands
__device__ __half g_xh[MTOT * DM];
__device__ __half g_winh[2 * EE * DM];
__device__ __half g_wselh[SELP * EE];         // rows 96..127 zero-padded
__device__ __half g_dtwh[EE * RR];
__device__ __half g_wouth[DM * EE];
__device__ __half g_uh[MTOT * EE];            // conv output (sel-GEMM A)
__device__ __half g_dtlh[MTOT * RR];          // dt_low (delta-GEMM A), lda=64
__device__ __half g_yh[MTOT * EE];            // scan output (out-GEMM A)

// ================= helpers =================
__device__ __forceinline__ uint32_t smem_u32(const void* p) {
    uint32_t a;
    asm("{ .reg .u64 t; cvta.to.shared.u64 t, %1; cvt.u32.u64 %0, t; }" : "=r"(a) : "l"(p));
    return a;
}
__device__ __forceinline__ void cp_async16(uint32_t dst, const void* src) {
    asm volatile("cp.async.cg.shared.global [%0], [%1], 16;" :: "r"(dst), "l"(src));
}
__device__ __forceinline__ void ldm_x4(uint32_t* r, uint32_t addr) {
    asm volatile("ldmatrix.sync.aligned.m8n8.x4.shared.b16 {%0,%1,%2,%3}, [%4];"
                 : "=r"(r[0]), "=r"(r[1]), "=r"(r[2]), "=r"(r[3]) : "r"(addr));
}
__device__ __forceinline__ void mma_f16(float* d, const uint32_t* a, const uint32_t* b) {
    asm volatile(
        "mma.sync.aligned.m16n8k16.row.col.f32.f16.f16.f32 "
        "{%0,%1,%2,%3}, {%4,%5,%6,%7}, {%8,%9}, {%0,%1,%2,%3};"
        : "+f"(d[0]), "+f"(d[1]), "+f"(d[2]), "+f"(d[3])
        : "r"(a[0]), "r"(a[1]), "r"(a[2]), "r"(a[3]), "r"(b[0]), "r"(b[1]));
}

// ---------------- fp32 -> fp16 convert pass (x + all weights) ----------------
static constexpr int C4_X    = MTOT * DM / 4;
static constexpr int C4_WIN  = 2 * EE * DM / 4;
static constexpr int C4_WSEL = SEL * EE / 4;
static constexpr int C4_DTW  = EE * RR / 4;
static constexpr int C4_WOUT = DM * EE / 4;
static constexpr int C4_PAD  = (SELP - SEL) * EE / 4;
static constexpr int C4_TOT  = C4_X + C4_WIN + C4_WSEL + C4_DTW + C4_WOUT + C4_PAD;

__global__ __launch_bounds__(256)
void to_half_kernel(const float4* __restrict__ x,    __half* __restrict__ xh,
                    const float4* __restrict__ win,  __half* __restrict__ winh,
                    const float4* __restrict__ wsel, __half* __restrict__ wselh,
                    const float4* __restrict__ dtw,  __half* __restrict__ dtwh,
                    const float4* __restrict__ wout, __half* __restrict__ wouth)
{
    int i = blockIdx.x * blockDim.x + threadIdx.x;
    if (i >= C4_TOT) return;
    const float4* src; __half* dst; int j = i;
    if (j < C4_X) { src = x; dst = xh; }
    else if ((j -= C4_X) < C4_WIN) { src = win; dst = winh; }
    else if ((j -= C4_WIN) < C4_WSEL) { src = wsel; dst = wselh; }
    else if ((j -= C4_WSEL) < C4_DTW) { src = dtw; dst = dtwh; }
    else if ((j -= C4_DTW) < C4_WOUT) { src = wout; dst = wouth; }
    else {  // zero pad rows 96..127 of wselh
        j -= C4_WOUT;
        reinterpret_cast<uint2*>(wselh + SEL * EE)[j] = make_uint2(0u, 0u);
        return;
    }
    float4 v = src[j];
    __half2 h01 = __floats2half2_rn(v.x, v.y);
    __half2 h23 = __floats2half2_rn(v.z, v.w);
    uint2 pk = make_uint2(*reinterpret_cast<uint32_t*>(&h01), *reinterpret_cast<uint32_t*>(&h23));
    reinterpret_cast<uint2*>(dst)[j] = pk;
}

// ================= fp16 tensor GEMM: C[M,N] = A[M,K] @ B[N,K]^T, fp32 accum =============
// Exact R6/R10 mainloop (best measured). BK = 64 fp16 (128B rows). smem: 16B unit at
// (c*ROWS + (r ^ c))*16, c = k/8. ldmatrix.x4 fragments; STAGES-deep cp.async pipeline.
// EPI: 0 = none; 1 = softplus(x+bias); 2 = dual write (fp32 cols<SEL into C with ldc,
// fp16 cols<RR into Ch with lda RR).
template<int BM, int BN, int WM, int WN, int STAGES, int EPI>
__global__ __launch_bounds__((BM / WM) * (BN / WN) * 32)
void mma_gemm(const __half* __restrict__ A, const __half* __restrict__ Bw,
              float* __restrict__ C, int K, int lda, int ldb, int ldc,
              const float* __restrict__ bias, __half* __restrict__ Ch)
{
    constexpr int WARPS_M = BM / WM;
    constexpr int WARPS_N = BN / WN;
    constexpr int THREADS = WARPS_M * WARPS_N * 32;
    constexpr int MT = WM / 16;
    constexpr int NT = WN / 8;
    constexpr int STAGE_B = (BM + BN) * 128;
    static_assert(NT % 2 == 0, "NT even");

    extern __shared__ char smem[];
    const uint32_t smem_b = smem_u32(smem);

    const int tid  = threadIdx.x;
    const int lane = tid & 31, wid = tid >> 5;
    const int wm = wid % WARPS_M, wn = wid / WARPS_M;
    const int qr = lane >> 2, kin = lane & 3;
    const int m0 = blockIdx.y * BM, n0 = blockIdx.x * BN;
    const int lrow = lane & 15, lcof = lane >> 4;

    float acc[MT][NT][4];
#pragma unroll
    for (int i = 0; i < MT; i++)
#pragma unroll
        for (int j = 0; j < NT; j++)
#pragma unroll
            for (int q = 0; q < 4; q++) acc[i][j][q] = 0.f;

    auto load_chunk = [&](int ck, int slot) {
        const int kt = ck * 64;
        const uint32_t ab = smem_b + slot * STAGE_B;
        const uint32_t bb = ab + BM * 128;
#pragma unroll
        for (int it = 0; it < BM * 8 / THREADS; it++) {
            int idx = tid + it * THREADS;
            int r = idx >> 3, c = idx & 7;
            cp_async16(ab + (uint32_t)(c * BM + (r ^ c)) * 16,
                       A + (size_t)(m0 + r) * lda + kt + c * 8);
        }
#pragma unroll
        for (int it = 0; it < BN * 8 / THREADS; it++) {
            int idx = tid + it * THREADS;
            int r = idx >> 3, c = idx & 7;
            cp_async16(bb + (uint32_t)(c * BN + (r ^ c)) * 16,
                       Bw + (size_t)(n0 + r) * ldb + kt + c * 8);
        }
        asm volatile("cp.async.commit_group;" ::: "memory");
    };

    const int nch = K / 64;
#pragma unroll
    for (int s = 0; s < STAGES - 1; s++)
        if (s < nch) load_chunk(s, s);

    for (int i = 0; i < nch; i++) {
        int w = nch - 1 - i;
        if (w > STAGES - 2) w = STAGES - 2;
        if      (w <= 0) asm volatile("cp.async.wait_group 0;" ::: "memory");
        else if (w == 1) asm volatile("cp.async.wait_group 1;" ::: "memory");
        else if (w == 2) asm volatile("cp.async.wait_group 2;" ::: "memory");
        else if (w == 3) asm volatile("cp.async.wait_group 3;" ::: "memory");
        else             asm volatile("cp.async.wait_group 4;" ::: "memory");
        __syncthreads();

        const uint32_t sa = smem_b + (i % STAGES) * STAGE_B;
        const uint32_t sb = sa + BM * 128;
#pragma unroll
        for (int ks = 0; ks < 4; ks++) {
            const int c = 2 * ks + lcof;
            uint32_t af[MT][4], bf[NT][2];
#pragma unroll
            for (int t = 0; t < MT; t++) {
                const int row = wm * WM + t * 16 + lrow;
                ldm_x4(af[t], sa + (uint32_t)(c * BM + (row ^ c)) * 16);
            }
#pragma unroll
            for (int p = 0; p < NT / 2; p++) {
                const int row = wn * WN + p * 16 + lrow;
                uint32_t r4[4];
                ldm_x4(r4, sb + (uint32_t)(c * BN + (row ^ c)) * 16);
                bf[2 * p][0] = r4[0]; bf[2 * p + 1][0] = r4[1];
                bf[2 * p][1] = r4[2]; bf[2 * p + 1][1] = r4[3];
            }
#pragma unroll
            for (int t = 0; t < MT; t++)
#pragma unroll
                for (int j = 0; j < NT; j++)
                    mma_f16(acc[t][j], af[t], bf[j]);
        }
        __syncthreads();

        const int pre = i + STAGES - 1;
        if (pre < nch) load_chunk(pre, pre % STAGES);
    }

    // ---------------- epilogue ----------------
#pragma unroll
    for (int t = 0; t < MT; t++) {
#pragma unroll
        for (int j = 0; j < NT; j++) {
            const int row = m0 + wm * WM + t * 16 + qr;
            const int col = n0 + wn * WN + j * 8 + kin * 2;
            float v0 = acc[t][j][0], v1 = acc[t][j][1];
            float v2 = acc[t][j][2], v3 = acc[t][j][3];
            if (EPI == 1) {
                const float b0 = bias[col], b1 = bias[col + 1];
                float x0 = v0 + b0, x1 = v1 + b1, x2 = v2 + b0, x3 = v3 + b1;
                v0 = (x0 > 20.f) ? x0 : log1pf(__expf(x0));
                v1 = (x1 > 20.f) ? x1 : log1pf(__expf(x1));
                v2 = (x2 > 20.f) ? x2 : log1pf(__expf(x2));
                v3 = (x3 > 20.f) ? x3 : log1pf(__expf(x3));
            }
            if (EPI == 2) {
                if (col < SEL) {
                    *reinterpret_cast<float2*>(C + (size_t)row * ldc + col)       = make_float2(v0, v1);
                    *reinterpret_cast<float2*>(C + (size_t)(row + 8) * ldc + col) = make_float2(v2, v3);
                }
                if (col < RR) {
                    *reinterpret_cast<__half2*>(Ch + (size_t)row * RR + col)
                        = __floats2half2_rn(v0, v1);
                    *reinterpret_cast<__half2*>(Ch + (size_t)(row + 8) * RR + col)
                        = __floats2half2_rn(v2, v3);
                }
            } else {
                *reinterpret_cast<float2*>(C + (size_t)row * ldc + col)       = make_float2(v0, v1);
                *reinterpret_cast<float2*>(C + (size_t)(row + 8) * ldc + col) = make_float2(v2, v3);
            }
        }
    }
}

// ---------------- causal depthwise conv1d (K=3) + bias + SiLU; also silu(z) -------------
// Per-batch: xz_b is this batch's [LEN, 2E] slice.
__global__ __launch_bounds__(256)
void conv_silu_kernel(const float* __restrict__ xz_b,
                      const float* __restrict__ cw,
                      const float* __restrict__ cb,
                      float2* __restrict__ ug_b,
                      __half* __restrict__ uh_b)
{
    int idx = blockIdx.x * blockDim.x + threadIdx.x;   // over LEN*E
    int e = idx % EE;
    int t = idx / EE;

    float acc = cb[e];
    float w0 = cw[e * 3 + 0], w1 = cw[e * 3 + 1], w2 = cw[e * 3 + 2];
    if (t >= 2) acc = fmaf(w0, xz_b[(size_t)(t - 2) * (2 * EE) + e], acc);
    if (t >= 1) acc = fmaf(w1, xz_b[(size_t)(t - 1) * (2 * EE) + e], acc);
    acc = fmaf(w2, xz_b[(size_t)t * (2 * EE) + e], acc);
    float s = acc / (1.f + __expf(-acc));              // silu(conv)
    float zv = xz_b[(size_t)t * (2 * EE) + EE + e];    // z
    float gz = zv / (1.f + __expf(-zv));               // silu(z)
    ug_b[idx] = make_float2(s, gz);
    uh_b[idx] = __float2half_rn(s);
}

// ---------------- selective scan (per batch): 3 LDG/iter, unconditional prefetch --------
__global__ __launch_bounds__(256)
void scan_kernel(const float* __restrict__ delta_b,
                 const float2* __restrict__ ug_b,
                 const float* __restrict__ dbc_b,
                 const float* __restrict__ A_log,
                 const float* __restrict__ D_param,
                 __half* __restrict__ yh_b)
{
    const int e    = blockIdx.x * (blockDim.x >> 4) + (threadIdx.x >> 4); // [0, E)
    const int lane = threadIdx.x & 31;
    const int n    = threadIdx.x & 15;

    const float An = -__expf(A_log[e * NN + n]);
    const float Dp = D_param[e];

    const float*  dptr = delta_b + e;
    const float2* gptr = ug_b + e;
    const float*  vptr = dbc_b + RR + lane;   // B|C packed: one 32-lane LDG
    __half*       yptr = yh_b + e;

    float h = 0.f;
    float  d0 = dptr[0], d1 = dptr[EE];
    float2 g0 = gptr[0], g1 = gptr[EE];
    float  v0 = vptr[0], v1 = vptr[SEL];

    for (int t = 0; t < LEN; t++) {
        // unconditional prefetch (scratch arrays padded by 2 rows; tail values unused)
        float  d2 = dptr[(size_t)(t + 2) * EE];
        float2 g2 = gptr[(size_t)(t + 2) * EE];
        float  v2 = vptr[(size_t)(t + 2) * SEL];

        const float Bc = __shfl_sync(0xffffffffu, v0, n);        // B_t[n]
        const float Cc = __shfl_sync(0xffffffffu, v0, n + 16);   // C_t[n]
        float dA = __expf(d0 * An);
        h = fmaf(dA, h, d0 * g0.x * Bc);
        float p = h * Cc;
        p += __shfl_xor_sync(0xffffffffu, p, 1);
        p += __shfl_xor_sync(0xffffffffu, p, 2);
        p += __shfl_xor_sync(0xffffffffu, p, 4);
        p += __shfl_xor_sync(0xffffffffu, p, 8);
        if (n == 0)
            yptr[(size_t)t * EE] = __float2half_rn((p + g0.x * Dp) * g0.y);
        d0 = d1; g0 = g1; v0 = v1;
        d1 = d2; g1 = g2; v1 = v2;
    }
}

// ---------------- launch: GEMM1 whole, then two concurrent per-batch chains -------------
extern "C" void kernel_launch(void* const* d_in, const int* in_sizes, int n_in,
                              void* d_out, int out_size)
{
    const float* x       = (const float*)d_in[0];
    const float* W_in    = (const float*)d_in[1];
    const float* conv_w  = (const float*)d_in[2];
    const float* conv_b  = (const float*)d_in[3];
    const float* W_sel   = (const float*)d_in[4];
    const float* dt_w    = (const float*)d_in[5];
    const float* dt_b    = (const float*)d_in[6];
    const float* A_log   = (const float*)d_in[7];
    const float* D_param = (const float*)d_in[8];
    const float* W_out   = (const float*)d_in[9];
    float* out = (float*)d_out;

    float *xz, *delta, *dbc;
    float2* ug;
    __half *xh, *winh, *wselh, *dtwh, *wouth, *uh, *dtlh, *yh;
    cudaGetSymbolAddress((void**)&xz,    g_xz);
    cudaGetSymbolAddress((void**)&ug,    g_ug);
    cudaGetSymbolAddress((void**)&delta, g_delta);
    cudaGetSymbolAddress((void**)&dbc,   g_dbc);
    cudaGetSymbolAddress((void**)&xh,    g_xh);
    cudaGetSymbolAddress((void**)&winh,  g_winh);
    cudaGetSymbolAddress((void**)&wselh, g_wselh);
    cudaGetSymbolAddress((void**)&dtwh,  g_dtwh);
    cudaGetSymbolAddress((void**)&wouth, g_wouth);
    cudaGetSymbolAddress((void**)&uh,    g_uh);
    cudaGetSymbolAddress((void**)&dtlh,  g_dtlh);
    cudaGetSymbolAddress((void**)&yh,    g_yh);

    // R10 kernel variants (best measured)
    auto* k_big = mma_gemm<128, 128, 32, 32, 4, 0>;   // 512 thr, 16 warps, 4 stages
    auto* k_dlt = mma_gemm<128, 128, 32, 32, 2, 1>;   // 512 thr, K=64 -> 1 chunk
    auto* k_sel = mma_gemm< 32, 128, 32, 16, 6, 2>;   // 256 thr, 6 stages, dual-write

    constexpr int SM_BIG = 4 * (128 + 128) * 128;  // 131072
    constexpr int SM_DLT = 2 * (128 + 128) * 128;  // 65536
    constexpr int SM_SEL = 6 * ( 32 + 128) * 128;  // 122880
    cudaFuncSetAttribute((const void*)k_big, cudaFuncAttributeMaxDynamicSharedMemorySize, SM_BIG);
    cudaFuncSetAttribute((const void*)k_dlt, cudaFuncAttributeMaxDynamicSharedMemorySize, SM_DLT);
    cudaFuncSetAttribute((const void*)k_sel, cudaFuncAttributeMaxDynamicSharedMemorySize, SM_SEL);

    // Fork/join plumbing (host objects only; created per call, never destroyed —
    // graph capture tolerates this, proven in R9).
    cudaStream_t s1;
    cudaStreamCreateWithFlags(&s1, cudaStreamNonBlocking);
    cudaEvent_t evFork, evJoin;
    cudaEventCreateWithFlags(&evFork, cudaEventDisableTiming);
    cudaEventCreateWithFlags(&evJoin, cudaEventDisableTiming);

    // 0) convert x + weights to fp16 (and zero-pad wselh)
    to_half_kernel<<<(C4_TOT + 255) / 256, 256>>>(
        (const float4*)x, xh, (const float4*)W_in, winh,
        (const float4*)W_sel, wselh, (const float4*)dt_w, dtwh,
        (const float4*)W_out, wouth);

    // 1) xz = x @ W_in^T   [4096, 4096], K=1024  (kept whole: best wave efficiency)
    k_big<<<dim3((2 * EE) / 128, MTOT / 128), 512, SM_BIG>>>(
        xh, winh, xz, DM, DM, DM, 2 * EE, nullptr, nullptr);

    // Fork: per-batch chains (conv -> sel -> delta -> scan -> GEMM6) are independent.
    cudaEventRecord(evFork, 0);
    cudaStreamWaitEvent(s1, evFork, 0);

    for (int b = 0; b < BSZ; b++) {
        cudaStream_t st = (b == 0) ? (cudaStream_t)0 : s1;
        const size_t mo = (size_t)b * LEN;   // row offset

        // 2) conv + silu + silu(z)
        conv_silu_kernel<<<(LEN * EE) / 256, 256, 0, st>>>(
            xz + mo * 2 * EE, conv_w, conv_b, ug + mo * EE, uh + mo * EE);

        // 3) dbc_b = u_b @ W_sel^T  [2048, 96(pad128)], K=2048  (+ fp16 dt_low)
        k_sel<<<dim3(1, LEN / 32), 256, SM_SEL, st>>>(
            uh + mo * EE, wselh, dbc + mo * SEL, EE, EE, EE, SEL, nullptr,
            dtlh + mo * RR);

        // 4) delta_b = softplus(dt_low_b @ dt_w^T + dt_b)  [2048, 2048], K=64
        k_dlt<<<dim3(EE / 128, LEN / 128), 512, SM_DLT, st>>>(
            dtlh + mo * RR, dtwh, delta + mo * EE, RR, RR, RR, EE, dt_b, nullptr);

        // 5) selective scan -> y_b (fp16)
        scan_kernel<<<EE / 16, 256, 0, st>>>(
            delta + mo * EE, ug + mo * EE, dbc + mo * SEL,
            A_log, D_param, yh + mo * EE);

        // 6) out_b = y_b @ W_out^T  [2048, 1024], K=2048  (128 CTAs = 1 clean wave)
        k_big<<<dim3(DM / 128, LEN / 128), 512, SM_BIG, st>>>(
            yh + mo * EE, wouth, out + mo * DM, EE, EE, EE, DM, nullptr, nullptr);
    }

    cudaEventRecord(evJoin, s1);
    cudaStreamWaitEvent(0, evJoin, 0);
}

// round 12
// speedup vs baseline: 1.1742x; 1.0251x over previous
#include <cuda_runtime.h>
#include <cuda_fp16.h>
#include <cstdint>

// Problem constants (ClassicMambaBlock: B=2, L=2048, Dm=1024, E=2048, N=16, R=64, K=3)
static constexpr int BSZ  = 2;
static constexpr int LEN  = 2048;
static constexpr int DM   = 1024;
static constexpr int EE   = 2048;
static constexpr int NN   = 16;
static constexpr int RR   = 64;
static constexpr int SEL  = RR + 2 * NN;   // 96
static constexpr int SELP = 128;           // padded to 128 for sel-GEMM tiling
static constexpr int MTOT = BSZ * LEN;     // 4096

// ---------------- scratch (no cudaMalloc allowed; +2 rows padding for scan prefetch) ----
__device__ float  g_xz[MTOT * 2 * EE];        // [M,4096]: cols [0,E)=xc, [E,2E)=z
__device__ float2 g_ug[(MTOT + 2) * EE];      // {u, silu(z)} per (t,e)
__device__ float  g_delta[(MTOT + 2) * EE];   // softplus(dt)
__device__ float  g_dbc[(MTOT + 2) * SEL];    // [M,96]: dt_low | B | C
// fp16 GEMM operands
__device__ __half g_xh[MTOT * DM];
__device__ __half g_winh[2 * EE * DM];
__device__ __half g_wselh[SELP * EE];         // rows 96..127 zero-padded
__device__ __half g_dtwh[EE * RR];
__device__ __half g_wouth[DM * EE];
__device__ __half g_uh[MTOT * EE];            // conv output (sel-GEMM A)
__device__ __half g_dtlh[MTOT * RR];          // dt_low (delta-GEMM A), lda=64
__device__ __half g_yh[MTOT * EE];            // scan output (out-GEMM A)

// ================= helpers =================
__device__ __forceinline__ uint32_t smem_u32(const void* p) {
    uint32_t a;
    asm("{ .reg .u64 t; cvta.to.shared.u64 t, %1; cvt.u32.u64 %0, t; }" : "=r"(a) : "l"(p));
    return a;
}
__device__ __forceinline__ void cp_async16(uint32_t dst, const void* src) {
    asm volatile("cp.async.cg.shared.global [%0], [%1], 16;" :: "r"(dst), "l"(src));
}
__device__ __forceinline__ void ldm_x4(uint32_t* r, uint32_t addr) {
    asm volatile("ldmatrix.sync.aligned.m8n8.x4.shared.b16 {%0,%1,%2,%3}, [%4];"
                 : "=r"(r[0]), "=r"(r[1]), "=r"(r[2]), "=r"(r[3]) : "r"(addr));
}
__device__ __forceinline__ void mma_f16(float* d, const uint32_t* a, const uint32_t* b) {
    asm volatile(
        "mma.sync.aligned.m16n8k16.row.col.f32.f16.f16.f32 "
        "{%0,%1,%2,%3}, {%4,%5,%6,%7}, {%8,%9}, {%0,%1,%2,%3};"
        : "+f"(d[0]), "+f"(d[1]), "+f"(d[2]), "+f"(d[3])
        : "r"(a[0]), "r"(a[1]), "r"(a[2]), "r"(a[3]), "r"(b[0]), "r"(b[1]));
}

// ---------------- fp32 -> fp16 convert pass (x + all weights) ----------------
static constexpr int C4_X    = MTOT * DM / 4;
static constexpr int C4_WIN  = 2 * EE * DM / 4;
static constexpr int C4_WSEL = SEL * EE / 4;
static constexpr int C4_DTW  = EE * RR / 4;
static constexpr int C4_WOUT = DM * EE / 4;
static constexpr int C4_PAD  = (SELP - SEL) * EE / 4;
static constexpr int C4_TOT  = C4_X + C4_WIN + C4_WSEL + C4_DTW + C4_WOUT + C4_PAD;

__global__ __launch_bounds__(256)
void to_half_kernel(const float4* __restrict__ x,    __half* __restrict__ xh,
                    const float4* __restrict__ win,  __half* __restrict__ winh,
                    const float4* __restrict__ wsel, __half* __restrict__ wselh,
                    const float4* __restrict__ dtw,  __half* __restrict__ dtwh,
                    const float4* __restrict__ wout, __half* __restrict__ wouth)
{
    int i = blockIdx.x * blockDim.x + threadIdx.x;
    if (i >= C4_TOT) return;
    const float4* src; __half* dst; int j = i;
    if (j < C4_X) { src = x; dst = xh; }
    else if ((j -= C4_X) < C4_WIN) { src = win; dst = winh; }
    else if ((j -= C4_WIN) < C4_WSEL) { src = wsel; dst = wselh; }
    else if ((j -= C4_WSEL) < C4_DTW) { src = dtw; dst = dtwh; }
    else if ((j -= C4_DTW) < C4_WOUT) { src = wout; dst = wouth; }
    else {  // zero pad rows 96..127 of wselh
        j -= C4_WOUT;
        reinterpret_cast<uint2*>(wselh + SEL * EE)[j] = make_uint2(0u, 0u);
        return;
    }
    float4 v = src[j];
    __half2 h01 = __floats2half2_rn(v.x, v.y);
    __half2 h23 = __floats2half2_rn(v.z, v.w);
    uint2 pk = make_uint2(*reinterpret_cast<uint32_t*>(&h01), *reinterpret_cast<uint32_t*>(&h23));
    reinterpret_cast<uint2*>(dst)[j] = pk;
}

// ================= fp16 tensor GEMM: C[M,N] = A[M,K] @ B[N,K]^T, fp32 accum =============
// Exact R6/R10 mainloop (best measured). BK = 64 fp16 (128B rows). smem: 16B unit at
// (c*ROWS + (r ^ c))*16, c = k/8. ldmatrix.x4 fragments; STAGES-deep cp.async pipeline.
// EPI: 0 = none; 1 = softplus(x+bias); 2 = dual write (fp32 cols<SEL into C with ldc,
// fp16 cols<RR into Ch with lda RR).
template<int BM, int BN, int WM, int WN, int STAGES, int EPI>
__global__ __launch_bounds__((BM / WM) * (BN / WN) * 32)
void mma_gemm(const __half* __restrict__ A, const __half* __restrict__ Bw,
              float* __restrict__ C, int K, int lda, int ldb, int ldc,
              const float* __restrict__ bias, __half* __restrict__ Ch)
{
    constexpr int WARPS_M = BM / WM;
    constexpr int WARPS_N = BN / WN;
    constexpr int THREADS = WARPS_M * WARPS_N * 32;
    constexpr int MT = WM / 16;
    constexpr int NT = WN / 8;
    constexpr int STAGE_B = (BM + BN) * 128;
    static_assert(NT % 2 == 0, "NT even");

    extern __shared__ char smem[];
    const uint32_t smem_b = smem_u32(smem);

    const int tid  = threadIdx.x;
    const int lane = tid & 31, wid = tid >> 5;
    const int wm = wid % WARPS_M, wn = wid / WARPS_M;
    const int qr = lane >> 2, kin = lane & 3;
    const int m0 = blockIdx.y * BM, n0 = blockIdx.x * BN;
    const int lrow = lane & 15, lcof = lane >> 4;

    float acc[MT][NT][4];
#pragma unroll
    for (int i = 0; i < MT; i++)
#pragma unroll
        for (int j = 0; j < NT; j++)
#pragma unroll
            for (int q = 0; q < 4; q++) acc[i][j][q] = 0.f;

    auto load_chunk = [&](int ck, int slot) {
        const int kt = ck * 64;
        const uint32_t ab = smem_b + slot * STAGE_B;
        const uint32_t bb = ab + BM * 128;
#pragma unroll
        for (int it = 0; it < BM * 8 / THREADS; it++) {
            int idx = tid + it * THREADS;
            int r = idx >> 3, c = idx & 7;
            cp_async16(ab + (uint32_t)(c * BM + (r ^ c)) * 16,
                       A + (size_t)(m0 + r) * lda + kt + c * 8);
        }
#pragma unroll
        for (int it = 0; it < BN * 8 / THREADS; it++) {
            int idx = tid + it * THREADS;
            int r = idx >> 3, c = idx & 7;
            cp_async16(bb + (uint32_t)(c * BN + (r ^ c)) * 16,
                       Bw + (size_t)(n0 + r) * ldb + kt + c * 8);
        }
        asm volatile("cp.async.commit_group;" ::: "memory");
    };

    const int nch = K / 64;
#pragma unroll
    for (int s = 0; s < STAGES - 1; s++)
        if (s < nch) load_chunk(s, s);

    for (int i = 0; i < nch; i++) {
        int w = nch - 1 - i;
        if (w > STAGES - 2) w = STAGES - 2;
        if      (w <= 0) asm volatile("cp.async.wait_group 0;" ::: "memory");
        else if (w == 1) asm volatile("cp.async.wait_group 1;" ::: "memory");
        else if (w == 2) asm volatile("cp.async.wait_group 2;" ::: "memory");
        else if (w == 3) asm volatile("cp.async.wait_group 3;" ::: "memory");
        else             asm volatile("cp.async.wait_group 4;" ::: "memory");
        __syncthreads();

        const uint32_t sa = smem_b + (i % STAGES) * STAGE_B;
        const uint32_t sb = sa + BM * 128;
#pragma unroll
        for (int ks = 0; ks < 4; ks++) {
            const int c = 2 * ks + lcof;
            uint32_t af[MT][4], bf[NT][2];
#pragma unroll
            for (int t = 0; t < MT; t++) {
                const int row = wm * WM + t * 16 + lrow;
                ldm_x4(af[t], sa + (uint32_t)(c * BM + (row ^ c)) * 16);
            }
#pragma unroll
            for (int p = 0; p < NT / 2; p++) {
                const int row = wn * WN + p * 16 + lrow;
                uint32_t r4[4];
                ldm_x4(r4, sb + (uint32_t)(c * BN + (row ^ c)) * 16);
                bf[2 * p][0] = r4[0]; bf[2 * p + 1][0] = r4[1];
                bf[2 * p][1] = r4[2]; bf[2 * p + 1][1] = r4[3];
            }
#pragma unroll
            for (int t = 0; t < MT; t++)
#pragma unroll
                for (int j = 0; j < NT; j++)
                    mma_f16(acc[t][j], af[t], bf[j]);
        }
        __syncthreads();

        const int pre = i + STAGES - 1;
        if (pre < nch) load_chunk(pre, pre % STAGES);
    }

    // ---------------- epilogue ----------------
#pragma unroll
    for (int t = 0; t < MT; t++) {
#pragma unroll
        for (int j = 0; j < NT; j++) {
            const int row = m0 + wm * WM + t * 16 + qr;
            const int col = n0 + wn * WN + j * 8 + kin * 2;
            float v0 = acc[t][j][0], v1 = acc[t][j][1];
            float v2 = acc[t][j][2], v3 = acc[t][j][3];
            if (EPI == 1) {
                const float b0 = bias[col], b1 = bias[col + 1];
                float x0 = v0 + b0, x1 = v1 + b1, x2 = v2 + b0, x3 = v3 + b1;
                v0 = (x0 > 20.f) ? x0 : log1pf(__expf(x0));
                v1 = (x1 > 20.f) ? x1 : log1pf(__expf(x1));
                v2 = (x2 > 20.f) ? x2 : log1pf(__expf(x2));
                v3 = (x3 > 20.f) ? x3 : log1pf(__expf(x3));
            }
            if (EPI == 2) {
                if (col < SEL) {
                    *reinterpret_cast<float2*>(C + (size_t)row * ldc + col)       = make_float2(v0, v1);
                    *reinterpret_cast<float2*>(C + (size_t)(row + 8) * ldc + col) = make_float2(v2, v3);
                }
                if (col < RR) {
                    *reinterpret_cast<__half2*>(Ch + (size_t)row * RR + col)
                        = __floats2half2_rn(v0, v1);
                    *reinterpret_cast<__half2*>(Ch + (size_t)(row + 8) * RR + col)
                        = __floats2half2_rn(v2, v3);
                }
            } else {
                *reinterpret_cast<float2*>(C + (size_t)row * ldc + col)       = make_float2(v0, v1);
                *reinterpret_cast<float2*>(C + (size_t)(row + 8) * ldc + col) = make_float2(v2, v3);
            }
        }
    }
}

// ---------------- causal depthwise conv1d (K=3) + bias + SiLU; also silu(z) -------------
// Per-batch: xz_b is this batch's [LEN, 2E] slice.
__global__ __launch_bounds__(256)
void conv_silu_kernel(const float* __restrict__ xz_b,
                      const float* __restrict__ cw,
                      const float* __restrict__ cb,
                      float2* __restrict__ ug_b,
                      __half* __restrict__ uh_b)
{
    int idx = blockIdx.x * blockDim.x + threadIdx.x;   // over LEN*E
    int e = idx % EE;
    int t = idx / EE;

    float acc = cb[e];
    float w0 = cw[e * 3 + 0], w1 = cw[e * 3 + 1], w2 = cw[e * 3 + 2];
    if (t >= 2) acc = fmaf(w0, xz_b[(size_t)(t - 2) * (2 * EE) + e], acc);
    if (t >= 1) acc = fmaf(w1, xz_b[(size_t)(t - 1) * (2 * EE) + e], acc);
    acc = fmaf(w2, xz_b[(size_t)t * (2 * EE) + e], acc);
    float s = acc / (1.f + __expf(-acc));              // silu(conv)
    float zv = xz_b[(size_t)t * (2 * EE) + EE + e];    // z
    float gz = zv / (1.f + __expf(-zv));               // silu(z)
    ug_b[idx] = make_float2(s, gz);
    uh_b[idx] = __float2half_rn(s);
}

// ---------------- selective scan (per batch): software-pipelined reduction --------------
// The y-reduction (4-deep shfl_xor chain, 104 cyc) is pipelined across iterations:
// each iteration issues ONE stage of 4 pending reductions (all shfls independent),
// so each 26-cyc shfl latency is covered by a full loop iteration. Store lags 3 iters.
__global__ __launch_bounds__(256)
void scan_kernel(const float* __restrict__ delta_b,
                 const float2* __restrict__ ug_b,
                 const float* __restrict__ dbc_b,
                 const float* __restrict__ A_log,
                 const float* __restrict__ D_param,
                 __half* __restrict__ yh_b)
{
    const int e    = blockIdx.x * (blockDim.x >> 4) + (threadIdx.x >> 4); // [0, E)
    const int lane = threadIdx.x & 31;
    const int n    = threadIdx.x & 15;

    const float An = -__expf(A_log[e * NN + n]);
    const float Dp = D_param[e];

    const float*  dptr = delta_b + e;
    const float2* gptr = ug_b + e;
    const float*  vptr = dbc_b + RR + lane;   // B|C packed: one 32-lane LDG
    __half*       yptr = yh_b + e;

    float h = 0.f;
    // data prefetch (depth 2; arrays padded by 2 rows)
    float  d0 = dptr[0], d1 = dptr[EE];
    float2 g0 = gptr[0], g1 = gptr[EE];
    float  v0 = vptr[0], v1 = vptr[SEL];

    // reduction pipeline registers (stage k of reductions started 1..3 iters ago)
    float r1 = 0.f, r2 = 0.f, r3 = 0.f;
    // (u, gz) history for deferred stores: H2 = t-3, H1 = t-2, H0 = t-1 (at iter t)
    float2 gH0 = make_float2(0.f, 0.f), gH1 = gH0, gH2 = gH0;

    for (int t = 0; t < LEN; t++) {
        // unconditional prefetch (padded rows are zero; values never stored)
        float  d2 = dptr[(size_t)(t + 2) * EE];
        float2 g2 = gptr[(size_t)(t + 2) * EE];
        float  v2 = vptr[(size_t)(t + 2) * SEL];

        const float Bc = __shfl_sync(0xffffffffu, v0, n);        // B_t[n]
        const float Cc = __shfl_sync(0xffffffffu, v0, n + 16);   // C_t[n]
        float dA = __expf(d0 * An);
        h = fmaf(dA, h, d0 * g0.x * Bc);
        float p = h * Cc;

        // pipelined reduction: one stage per pending sum (4 independent shfls)
        float s4 = r3 + __shfl_xor_sync(0xffffffffu, r3, 8);     // completes p_{t-3}
        float n3 = r2 + __shfl_xor_sync(0xffffffffu, r2, 4);
        float n2 = r1 + __shfl_xor_sync(0xffffffffu, r1, 2);
        float n1 = p  + __shfl_xor_sync(0xffffffffu, p,  1);
        if (n == 0 && t >= 3)
            yptr[(size_t)(t - 3) * EE] = __float2half_rn((s4 + gH2.x * Dp) * gH2.y);
        r3 = n3; r2 = n2; r1 = n1;
        gH2 = gH1; gH1 = gH0; gH0 = g0;

        d0 = d1; g0 = g1; v0 = v1;
        d1 = d2; g1 = g2; v1 = v2;
    }

    // drain: flush the 3 pending reductions (t = LEN-3 .. LEN-1)
#pragma unroll
    for (int k = 0; k < 3; k++) {
        float s4 = r3 + __shfl_xor_sync(0xffffffffu, r3, 8);
        float n3 = r2 + __shfl_xor_sync(0xffffffffu, r2, 4);
        float n2 = r1 + __shfl_xor_sync(0xffffffffu, r1, 2);
        if (n == 0)
            yptr[(size_t)(LEN - 3 + k) * EE] = __float2half_rn((s4 + gH2.x * Dp) * gH2.y);
        r3 = n3; r2 = n2;
        gH2 = gH1; gH1 = gH0;
    }
}

// ---------------- launch: GEMM1 whole, then two concurrent per-batch chains -------------
extern "C" void kernel_launch(void* const* d_in, const int* in_sizes, int n_in,
                              void* d_out, int out_size)
{
    const float* x       = (const float*)d_in[0];
    const float* W_in    = (const float*)d_in[1];
    const float* conv_w  = (const float*)d_in[2];
    const float* conv_b  = (const float*)d_in[3];
    const float* W_sel   = (const float*)d_in[4];
    const float* dt_w    = (const float*)d_in[5];
    const float* dt_b    = (const float*)d_in[6];
    const float* A_log   = (const float*)d_in[7];
    const float* D_param = (const float*)d_in[8];
    const float* W_out   = (const float*)d_in[9];
    float* out = (float*)d_out;

    float *xz, *delta, *dbc;
    float2* ug;
    __half *xh, *winh, *wselh, *dtwh, *wouth, *uh, *dtlh, *yh;
    cudaGetSymbolAddress((void**)&xz,    g_xz);
    cudaGetSymbolAddress((void**)&ug,    g_ug);
    cudaGetSymbolAddress((void**)&delta, g_delta);
    cudaGetSymbolAddress((void**)&dbc,   g_dbc);
    cudaGetSymbolAddress((void**)&xh,    g_xh);
    cudaGetSymbolAddress((void**)&winh,  g_winh);
    cudaGetSymbolAddress((void**)&wselh, g_wselh);
    cudaGetSymbolAddress((void**)&dtwh,  g_dtwh);
    cudaGetSymbolAddress((void**)&wouth, g_wouth);
    cudaGetSymbolAddress((void**)&uh,    g_uh);
    cudaGetSymbolAddress((void**)&dtlh,  g_dtlh);
    cudaGetSymbolAddress((void**)&yh,    g_yh);

    // R10/R11 kernel variants (best measured)
    auto* k_big = mma_gemm<128, 128, 32, 32, 4, 0>;   // 512 thr, 16 warps, 4 stages
    auto* k_dlt = mma_gemm<128, 128, 32, 32, 2, 1>;   // 512 thr, K=64 -> 1 chunk
    auto* k_sel = mma_gemm< 32, 128, 32, 16, 6, 2>;   // 256 thr, 6 stages, dual-write

    constexpr int SM_BIG = 4 * (128 + 128) * 128;  // 131072
    constexpr int SM_DLT = 2 * (128 + 128) * 128;  // 65536
    constexpr int SM_SEL = 6 * ( 32 + 128) * 128;  // 122880
    cudaFuncSetAttribute((const void*)k_big, cudaFuncAttributeMaxDynamicSharedMemorySize, SM_BIG);
    cudaFuncSetAttribute((const void*)k_dlt, cudaFuncAttributeMaxDynamicSharedMemorySize, SM_DLT);
    cudaFuncSetAttribute((const void*)k_sel, cudaFuncAttributeMaxDynamicSharedMemorySize, SM_SEL);

    // Fork/join plumbing (host objects only; created per call, never destroyed —
    // graph capture tolerates this, proven in R9/R11).
    cudaStream_t s1;
    cudaStreamCreateWithFlags(&s1, cudaStreamNonBlocking);
    cudaEvent_t evFork, evJoin;
    cudaEventCreateWithFlags(&evFork, cudaEventDisableTiming);
    cudaEventCreateWithFlags(&evJoin, cudaEventDisableTiming);

    // 0) convert x + weights to fp16 (and zero-pad wselh)
    to_half_kernel<<<(C4_TOT + 255) / 256, 256>>>(
        (const float4*)x, xh, (const float4*)W_in, winh,
        (const float4*)W_sel, wselh, (const float4*)dt_w, dtwh,
        (const float4*)W_out, wouth);

    // 1) xz = x @ W_in^T   [4096, 4096], K=1024  (kept whole: best wave efficiency)
    k_big<<<dim3((2 * EE) / 128, MTOT / 128), 512, SM_BIG>>>(
        xh, winh, xz, DM, DM, DM, 2 * EE, nullptr, nullptr);

    // Fork: per-batch chains (conv -> sel -> delta -> scan -> GEMM6) are independent.
    cudaEventRecord(evFork, 0);
    cudaStreamWaitEvent(s1, evFork, 0);

    for (int b = 0; b < BSZ; b++) {
        cudaStream_t st = (b == 0) ? (cudaStream_t)0 : s1;
        const size_t mo = (size_t)b * LEN;   // row offset

        // 2) conv + silu + silu(z)
        conv_silu_kernel<<<(LEN * EE) / 256, 256, 0, st>>>(
            xz + mo * 2 * EE, conv_w, conv_b, ug + mo * EE, uh + mo * EE);

        // 3) dbc_b = u_b @ W_sel^T  [2048, 96(pad128)], K=2048  (+ fp16 dt_low)
        k_sel<<<dim3(1, LEN / 32), 256, SM_SEL, st>>>(
            uh + mo * EE, wselh, dbc + mo * SEL, EE, EE, EE, SEL, nullptr,
            dtlh + mo * RR);

        // 4) delta_b = softplus(dt_low_b @ dt_w^T + dt_b)  [2048, 2048], K=64
        k_dlt<<<dim3(EE / 128, LEN / 128), 512, SM_DLT, st>>>(
            dtlh + mo * RR, dtwh, delta + mo * EE, RR, RR, RR, EE, dt_b, nullptr);

        // 5) selective scan (pipelined reduction) -> y_b (fp16)
        scan_kernel<<<EE / 16, 256, 0, st>>>(
            delta + mo * EE, ug + mo * EE, dbc + mo * SEL,
            A_log, D_param, yh + mo * EE);

        // 6) out_b = y_b @ W_out^T  [2048, 1024], K=2048
        k_big<<<dim3(DM / 128, LEN / 128), 512, SM_BIG, st>>>(
            yh + mo * EE, wouth, out + mo * DM, EE, EE, EE, DM, nullptr, nullptr);
    }

    cudaEventRecord(evJoin, s1);
    cudaStreamWaitEvent(0, evJoin, 0);
}

// round 14
// speedup vs baseline: 1.2127x; 1.0328x over previous
#include <cuda_runtime.h>
#include <cuda_fp16.h>
#include <cstdint>

// Problem constants (ClassicMambaBlock: B=2, L=2048, Dm=1024, E=2048, N=16, R=64, K=3)
static constexpr int BSZ  = 2;
static constexpr int LEN  = 2048;
static constexpr int DM   = 1024;
static constexpr int EE   = 2048;
static constexpr int NN   = 16;
static constexpr int RR   = 64;
static constexpr int SEL  = RR + 2 * NN;   // 96
static constexpr int SELP = 128;           // padded to 128 for sel-GEMM tiling
static constexpr int MTOT = BSZ * LEN;     // 4096

// ---------------- scratch (no cudaMalloc allowed; +2 rows padding for scan prefetch) ----
__device__ float  g_xz[MTOT * 2 * EE];        // [M,4096]: cols [0,E)=xc, [E,2E)=z
__device__ float2 g_ug[(MTOT + 2) * EE];      // {u, silu(z)} per (t,e)
__device__ float  g_delta[(MTOT + 2) * EE];   // softplus(dt)
__device__ float  g_dbc[(MTOT + 2) * SEL];    // [M,96]: dt_low | B | C
// fp16 GEMM operands
__device__ __half g_xh[MTOT * DM];
__device__ __half g_winh[2 * EE * DM];
__device__ __half g_wselh[SELP * EE];         // rows 96..127 zero-padded
__device__ __half g_dtwh[EE * RR];
__device__ __half g_wouth[DM * EE];
__device__ __half g_uh[MTOT * EE];            // conv output (sel-GEMM A)
__device__ __half g_dtlh[MTOT * RR];          // dt_low (delta-GEMM A), lda=64
__device__ __half g_yh[MTOT * EE];            // scan output (out-GEMM A)

// ================= helpers =================
__device__ __forceinline__ uint32_t smem_u32(const void* p) {
    uint32_t a;
    asm("{ .reg .u64 t; cvta.to.shared.u64 t, %1; cvt.u32.u64 %0, t; }" : "=r"(a) : "l"(p));
    return a;
}
__device__ __forceinline__ void cp_async16(uint32_t dst, const void* src) {
    asm volatile("cp.async.cg.shared.global [%0], [%1], 16;" :: "r"(dst), "l"(src));
}
__device__ __forceinline__ void ldm_x4(uint32_t* r, uint32_t addr) {
    asm volatile("ldmatrix.sync.aligned.m8n8.x4.shared.b16 {%0,%1,%2,%3}, [%4];"
                 : "=r"(r[0]), "=r"(r[1]), "=r"(r[2]), "=r"(r[3]) : "r"(addr));
}
__device__ __forceinline__ void mma_f16(float* d, const uint32_t* a, const uint32_t* b) {
    asm volatile(
        "mma.sync.aligned.m16n8k16.row.col.f32.f16.f16.f32 "
        "{%0,%1,%2,%3}, {%4,%5,%6,%7}, {%8,%9}, {%0,%1,%2,%3};"
        : "+f"(d[0]), "+f"(d[1]), "+f"(d[2]), "+f"(d[3])
        : "r"(a[0]), "r"(a[1]), "r"(a[2]), "r"(a[3]), "r"(b[0]), "r"(b[1]));
}

// ---------------- fp32 -> fp16 convert: critical (x, W_in) + deferred (rest) ------------
static constexpr int C4_X    = MTOT * DM / 4;
static constexpr int C4_WIN  = 2 * EE * DM / 4;
static constexpr int C4_CRIT = C4_X + C4_WIN;
static constexpr int C4_WSEL = SEL * EE / 4;
static constexpr int C4_DTW  = EE * RR / 4;
static constexpr int C4_WOUT = DM * EE / 4;
static constexpr int C4_PAD  = (SELP - SEL) * EE / 4;
static constexpr int C4_REST = C4_WSEL + C4_DTW + C4_WOUT + C4_PAD;

__device__ __forceinline__ void cvt_store(const float4* src, __half* dst, int j) {
    float4 v = src[j];
    __half2 h01 = __floats2half2_rn(v.x, v.y);
    __half2 h23 = __floats2half2_rn(v.z, v.w);
    uint2 pk = make_uint2(*reinterpret_cast<uint32_t*>(&h01), *reinterpret_cast<uint32_t*>(&h23));
    reinterpret_cast<uint2*>(dst)[j] = pk;
}

__global__ __launch_bounds__(256)
void to_half_crit(const float4* __restrict__ x,   __half* __restrict__ xh,
                  const float4* __restrict__ win, __half* __restrict__ winh)
{
    int i = blockIdx.x * blockDim.x + threadIdx.x;
    if (i >= C4_CRIT) return;
    if (i < C4_X) cvt_store(x, xh, i);
    else          cvt_store(win, winh, i - C4_X);
}

__global__ __launch_bounds__(256)
void to_half_rest(const float4* __restrict__ wsel, __half* __restrict__ wselh,
                  const float4* __restrict__ dtw,  __half* __restrict__ dtwh,
                  const float4* __restrict__ wout, __half* __restrict__ wouth)
{
    int i = blockIdx.x * blockDim.x + threadIdx.x;
    if (i >= C4_REST) return;
    int j = i;
    if (j < C4_WSEL) { cvt_store(wsel, wselh, j); return; }
    if ((j -= C4_WSEL) < C4_DTW) { cvt_store(dtw, dtwh, j); return; }
    if ((j -= C4_DTW) < C4_WOUT) { cvt_store(wout, wouth, j); return; }
    j -= C4_WOUT;   // zero pad rows 96..127 of wselh
    reinterpret_cast<uint2*>(wselh + SEL * EE)[j] = make_uint2(0u, 0u);
}

// ================= fp16 tensor GEMM: C[M,N] = A[M,K] @ B[N,K]^T, fp32 accum =============
// R6/R10 mainloop. BK = 64 fp16 (128B rows). smem: 16B unit at (c*ROWS + (r ^ c))*16,
// c = k/8. ldmatrix.x4 fragments; STAGES-deep cp.async pipeline.
// EPI: 0 = none; 1 = softplus(x+bias); 2 = dual write (fp32 cols<SEL into C with ldc,
// fp16 cols<RR into Ch with lda RR).
template<int BM, int BN, int WM, int WN, int STAGES, int EPI>
__global__ __launch_bounds__((BM / WM) * (BN / WN) * 32)
void mma_gemm(const __half* __restrict__ A, const __half* __restrict__ Bw,
              float* __restrict__ C, int K, int lda, int ldb, int ldc,
              const float* __restrict__ bias, __half* __restrict__ Ch)
{
    constexpr int WARPS_M = BM / WM;
    constexpr int WARPS_N = BN / WN;
    constexpr int THREADS = WARPS_M * WARPS_N * 32;
    constexpr int MT = WM / 16;
    constexpr int NT = WN / 8;
    constexpr int STAGE_B = (BM + BN) * 128;
    static_assert(NT % 2 == 0, "NT even");

    extern __shared__ char smem[];
    const uint32_t smem_b = smem_u32(smem);

    const int tid  = threadIdx.x;
    const int lane = tid & 31, wid = tid >> 5;
    const int wm = wid % WARPS_M, wn = wid / WARPS_M;
    const int qr = lane >> 2, kin = lane & 3;
    const int m0 = blockIdx.y * BM, n0 = blockIdx.x * BN;
    const int lrow = lane & 15, lcof = lane >> 4;

    float acc[MT][NT][4];
#pragma unroll
    for (int i = 0; i < MT; i++)
#pragma unroll
        for (int j = 0; j < NT; j++)
#pragma unroll
            for (int q = 0; q < 4; q++) acc[i][j][q] = 0.f;

    auto load_chunk = [&](int ck, int slot) {
        const int kt = ck * 64;
        const uint32_t ab = smem_b + slot * STAGE_B;
        const uint32_t bb = ab + BM * 128;
#pragma unroll
        for (int it = 0; it < BM * 8 / THREADS; it++) {
            int idx = tid + it * THREADS;
            int r = idx >> 3, c = idx & 7;
            cp_async16(ab + (uint32_t)(c * BM + (r ^ c)) * 16,
                       A + (size_t)(m0 + r) * lda + kt + c * 8);
        }
#pragma unroll
        for (int it = 0; it < BN * 8 / THREADS; it++) {
            int idx = tid + it * THREADS;
            int r = idx >> 3, c = idx & 7;
            cp_async16(bb + (uint32_t)(c * BN + (r ^ c)) * 16,
                       Bw + (size_t)(n0 + r) * ldb + kt + c * 8);
        }
        asm volatile("cp.async.commit_group;" ::: "memory");
    };

    const int nch = K / 64;
#pragma unroll
    for (int s = 0; s < STAGES - 1; s++)
        if (s < nch) load_chunk(s, s);

    for (int i = 0; i < nch; i++) {
        int w = nch - 1 - i;
        if (w > STAGES - 2) w = STAGES - 2;
        if      (w <= 0) asm volatile("cp.async.wait_group 0;" ::: "memory");
        else if (w == 1) asm volatile("cp.async.wait_group 1;" ::: "memory");
        else if (w == 2) asm volatile("cp.async.wait_group 2;" ::: "memory");
        else if (w == 3) asm volatile("cp.async.wait_group 3;" ::: "memory");
        else             asm volatile("cp.async.wait_group 4;" ::: "memory");
        __syncthreads();

        const uint32_t sa = smem_b + (i % STAGES) * STAGE_B;
        const uint32_t sb = sa + BM * 128;
#pragma unroll
        for (int ks = 0; ks < 4; ks++) {
            const int c = 2 * ks + lcof;
            uint32_t af[MT][4], bf[NT][2];
#pragma unroll
            for (int t = 0; t < MT; t++) {
                const int row = wm * WM + t * 16 + lrow;
                ldm_x4(af[t], sa + (uint32_t)(c * BM + (row ^ c)) * 16);
            }
#pragma unroll
            for (int p = 0; p < NT / 2; p++) {
                const int row = wn * WN + p * 16 + lrow;
                uint32_t r4[4];
                ldm_x4(r4, sb + (uint32_t)(c * BN + (row ^ c)) * 16);
                bf[2 * p][0] = r4[0]; bf[2 * p + 1][0] = r4[1];
                bf[2 * p][1] = r4[2]; bf[2 * p + 1][1] = r4[3];
            }
#pragma unroll
            for (int t = 0; t < MT; t++)
#pragma unroll
                for (int j = 0; j < NT; j++)
                    mma_f16(acc[t][j], af[t], bf[j]);
        }
        __syncthreads();

        const int pre = i + STAGES - 1;
        if (pre < nch) load_chunk(pre, pre % STAGES);
    }

    // ---------------- epilogue ----------------
#pragma unroll
    for (int t = 0; t < MT; t++) {
#pragma unroll
        for (int j = 0; j < NT; j++) {
            const int row = m0 + wm * WM + t * 16 + qr;
            const int col = n0 + wn * WN + j * 8 + kin * 2;
            float v0 = acc[t][j][0], v1 = acc[t][j][1];
            float v2 = acc[t][j][2], v3 = acc[t][j][3];
            if (EPI == 1) {
                const float b0 = bias[col], b1 = bias[col + 1];
                float x0 = v0 + b0, x1 = v1 + b1, x2 = v2 + b0, x3 = v3 + b1;
                v0 = (x0 > 20.f) ? x0 : log1pf(__expf(x0));
                v1 = (x1 > 20.f) ? x1 : log1pf(__expf(x1));
                v2 = (x2 > 20.f) ? x2 : log1pf(__expf(x2));
                v3 = (x3 > 20.f) ? x3 : log1pf(__expf(x3));
            }
            if (EPI == 2) {
                if (col < SEL) {
                    *reinterpret_cast<float2*>(C + (size_t)row * ldc + col)       = make_float2(v0, v1);
                    *reinterpret_cast<float2*>(C + (size_t)(row + 8) * ldc + col) = make_float2(v2, v3);
                }
                if (col < RR) {
                    *reinterpret_cast<__half2*>(Ch + (size_t)row * RR + col)
                        = __floats2half2_rn(v0, v1);
                    *reinterpret_cast<__half2*>(Ch + (size_t)(row + 8) * RR + col)
                        = __floats2half2_rn(v2, v3);
                }
            } else {
                *reinterpret_cast<float2*>(C + (size_t)row * ldc + col)       = make_float2(v0, v1);
                *reinterpret_cast<float2*>(C + (size_t)(row + 8) * ldc + col) = make_float2(v2, v3);
            }
        }
    }
}

// ---------------- causal depthwise conv1d (K=3) + bias + SiLU; also silu(z) -------------
__global__ __launch_bounds__(256)
void conv_silu_kernel(const float* __restrict__ xz_b,
                      const float* __restrict__ cw,
                      const float* __restrict__ cb,
                      float2* __restrict__ ug_b,
                      __half* __restrict__ uh_b)
{
    int idx = blockIdx.x * blockDim.x + threadIdx.x;   // over LEN*E
    int e = idx % EE;
    int t = idx / EE;

    float acc = cb[e];
    float w0 = cw[e * 3 + 0], w1 = cw[e * 3 + 1], w2 = cw[e * 3 + 2];
    if (t >= 2) acc = fmaf(w0, xz_b[(size_t)(t - 2) * (2 * EE) + e], acc);
    if (t >= 1) acc = fmaf(w1, xz_b[(size_t)(t - 1) * (2 * EE) + e], acc);
    acc = fmaf(w2, xz_b[(size_t)t * (2 * EE) + e], acc);
    float s = acc / (1.f + __expf(-acc));              // silu(conv)
    float zv = xz_b[(size_t)t * (2 * EE) + EE + e];    // z
    float gz = zv / (1.f + __expf(-zv));               // silu(z)
    ug_b[idx] = make_float2(s, gz);
    uh_b[idx] = __float2half_rn(s);
}

// ---------------- selective scan (per batch): software-pipelined reduction --------------
__global__ __launch_bounds__(256)
void scan_kernel(const float* __restrict__ delta_b,
                 const float2* __restrict__ ug_b,
                 const float* __restrict__ dbc_b,
                 const float* __restrict__ A_log,
                 const float* __restrict__ D_param,
                 __half* __restrict__ yh_b)
{
    const int e    = blockIdx.x * (blockDim.x >> 4) + (threadIdx.x >> 4); // [0, E)
    const int lane = threadIdx.x & 31;
    const int n    = threadIdx.x & 15;

    const float An = -__expf(A_log[e * NN + n]);
    const float Dp = D_param[e];

    const float*  dptr = delta_b + e;
    const float2* gptr = ug_b + e;
    const float*  vptr = dbc_b + RR + lane;   // B|C packed: one 32-lane LDG
    __half*       yptr = yh_b + e;

    float h = 0.f;
    float  d0 = dptr[0], d1 = dptr[EE];
    float2 g0 = gptr[0], g1 = gptr[EE];
    float  v0 = vptr[0], v1 = vptr[SEL];

    float r1 = 0.f, r2 = 0.f, r3 = 0.f;
    float2 gH0 = make_float2(0.f, 0.f), gH1 = gH0, gH2 = gH0;

    for (int t = 0; t < LEN; t++) {
        float  d2 = dptr[(size_t)(t + 2) * EE];
        float2 g2 = gptr[(size_t)(t + 2) * EE];
        float  v2 = vptr[(size_t)(t + 2) * SEL];

        const float Bc = __shfl_sync(0xffffffffu, v0, n);
        const float Cc = __shfl_sync(0xffffffffu, v0, n + 16);
        float dA = __expf(d0 * An);
        h = fmaf(dA, h, d0 * g0.x * Bc);
        float p = h * Cc;

        float s4 = r3 + __shfl_xor_sync(0xffffffffu, r3, 8);
        float n3 = r2 + __shfl_xor_sync(0xffffffffu, r2, 4);
        float n2 = r1 + __shfl_xor_sync(0xffffffffu, r1, 2);
        float n1 = p  + __shfl_xor_sync(0xffffffffu, p,  1);
        if (n == 0 && t >= 3)
            yptr[(size_t)(t - 3) * EE] = __float2half_rn((s4 + gH2.x * Dp) * gH2.y);
        r3 = n3; r2 = n2; r1 = n1;
        gH2 = gH1; gH1 = gH0; gH0 = g0;

        d0 = d1; g0 = g1; v0 = v1;
        d1 = d2; g1 = g2; v1 = v2;
    }

#pragma unroll
    for (int k = 0; k < 3; k++) {
        float s4 = r3 + __shfl_xor_sync(0xffffffffu, r3, 8);
        float n3 = r2 + __shfl_xor_sync(0xffffffffu, r2, 4);
        float n2 = r1 + __shfl_xor_sync(0xffffffffu, r1, 2);
        if (n == 0)
            yptr[(size_t)(LEN - 3 + k) * EE] = __float2half_rn((s4 + gH2.x * Dp) * gH2.y);
        r3 = n3; r2 = n2;
        gH2 = gH1; gH1 = gH0;
    }
}

// ---------------- launch: legal capture topology (all s1 work forked from s0) -----------
extern "C" void kernel_launch(void* const* d_in, const int* in_sizes, int n_in,
                              void* d_out, int out_size)
{
    const float* x       = (const float*)d_in[0];
    const float* W_in    = (const float*)d_in[1];
    const float* conv_w  = (const float*)d_in[2];
    const float* conv_b  = (const float*)d_in[3];
    const float* W_sel   = (const float*)d_in[4];
    const float* dt_w    = (const float*)d_in[5];
    const float* dt_b    = (const float*)d_in[6];
    const float* A_log   = (const float*)d_in[7];
    const float* D_param = (const float*)d_in[8];
    const float* W_out   = (const float*)d_in[9];
    float* out = (float*)d_out;

    float *xz, *delta, *dbc;
    float2* ug;
    __half *xh, *winh, *wselh, *dtwh, *wouth, *uh, *dtlh, *yh;
    cudaGetSymbolAddress((void**)&xz,    g_xz);
    cudaGetSymbolAddress((void**)&ug,    g_ug);
    cudaGetSymbolAddress((void**)&delta, g_delta);
    cudaGetSymbolAddress((void**)&dbc,   g_dbc);
    cudaGetSymbolAddress((void**)&xh,    g_xh);
    cudaGetSymbolAddress((void**)&winh,  g_winh);
    cudaGetSymbolAddress((void**)&wselh, g_wselh);
    cudaGetSymbolAddress((void**)&dtwh,  g_dtwh);
    cudaGetSymbolAddress((void**)&wouth, g_wouth);
    cudaGetSymbolAddress((void**)&uh,    g_uh);
    cudaGetSymbolAddress((void**)&dtlh,  g_dtlh);
    cudaGetSymbolAddress((void**)&yh,    g_yh);

    // kernel variants
    auto* k_g1  = mma_gemm<256, 128, 64, 32, 4, 0>;   // 512 thr, big-tile experiment
    auto* k_g6  = mma_gemm<128, 128, 32, 32, 4, 0>;   // R12 config for GEMM6
    auto* k_dlt = mma_gemm<128, 128, 32, 32, 2, 1>;   // K=64 -> 1 chunk
    auto* k_sel = mma_gemm< 32, 128, 32, 16, 6, 2>;   // 256 thr, 6 stages, dual-write

    constexpr int SM_G1  = 4 * (256 + 128) * 128;  // 196608
    constexpr int SM_G6  = 4 * (128 + 128) * 128;  // 131072
    constexpr int SM_DLT = 2 * (128 + 128) * 128;  // 65536
    constexpr int SM_SEL = 6 * ( 32 + 128) * 128;  // 122880
    cudaFuncSetAttribute((const void*)k_g1,  cudaFuncAttributeMaxDynamicSharedMemorySize, SM_G1);
    cudaFuncSetAttribute((const void*)k_g6,  cudaFuncAttributeMaxDynamicSharedMemorySize, SM_G6);
    cudaFuncSetAttribute((const void*)k_dlt, cudaFuncAttributeMaxDynamicSharedMemorySize, SM_DLT);
    cudaFuncSetAttribute((const void*)k_sel, cudaFuncAttributeMaxDynamicSharedMemorySize, SM_SEL);

    // Fork/join plumbing (host objects only; never destroyed — capture-safe, proven R9-R12).
    cudaStream_t s1;
    cudaStreamCreateWithFlags(&s1, cudaStreamNonBlocking);
    cudaEvent_t evFork0, evFork1, evRest, evJoin;
    cudaEventCreateWithFlags(&evFork0, cudaEventDisableTiming);
    cudaEventCreateWithFlags(&evFork1, cudaEventDisableTiming);
    cudaEventCreateWithFlags(&evRest,  cudaEventDisableTiming);
    cudaEventCreateWithFlags(&evJoin,  cudaEventDisableTiming);

    // 0a) critical convert (x, W_in) on s0
    to_half_crit<<<(C4_CRIT + 255) / 256, 256>>>(
        (const float4*)x, xh, (const float4*)W_in, winh);

    // Fork s1 from s0 (AFTER s0 has captured work — this ordering is what R13 broke).
    cudaEventRecord(evFork0, 0);
    cudaStreamWaitEvent(s1, evFork0, 0);

    // 0b) deferred weight convert on s1, overlapping G1 on s0
    to_half_rest<<<(C4_REST + 255) / 256, 256, 0, s1>>>(
        (const float4*)W_sel, wselh, (const float4*)dt_w, dtwh,
        (const float4*)W_out, wouth);
    cudaEventRecord(evRest, s1);

    // 1) xz = x @ W_in^T   [4096, 4096], K=1024, 256x128 tiles (512 CTAs)
    k_g1<<<dim3((2 * EE) / 128, MTOT / 256), 512, SM_G1>>>(
        xh, winh, xz, DM, DM, DM, 2 * EE, nullptr, nullptr);

    // Fork per-batch chains: b=1 chain on s1 must see G1's output.
    cudaEventRecord(evFork1, 0);
    cudaStreamWaitEvent(s1, evFork1, 0);
    // s0's chain needs the deferred weights from s1.
    cudaStreamWaitEvent(0, evRest, 0);

    for (int b = 0; b < BSZ; b++) {
        cudaStream_t st = (b == 0) ? (cudaStream_t)0 : s1;
        const size_t mo = (size_t)b * LEN;

        // 2) conv + silu + silu(z)
        conv_silu_kernel<<<(LEN * EE) / 256, 256, 0, st>>>(
            xz + mo * 2 * EE, conv_w, conv_b, ug + mo * EE, uh + mo * EE);

        // 3) dbc_b = u_b @ W_sel^T  [2048, 96(pad128)], K=2048  (+ fp16 dt_low)
        k_sel<<<dim3(1, LEN / 32), 256, SM_SEL, st>>>(
            uh + mo * EE, wselh, dbc + mo * SEL, EE, EE, EE, SEL, nullptr,
            dtlh + mo * RR);

        // 4) delta_b = softplus(dt_low_b @ dt_w^T + dt_b)  [2048, 2048], K=64
        k_dlt<<<dim3(EE / 128, LEN / 128), 512, SM_DLT, st>>>(
            dtlh + mo * RR, dtwh, delta + mo * EE, RR, RR, RR, EE, dt_b, nullptr);

        // 5) selective scan (pipelined reduction) -> y_b (fp16)
        scan_kernel<<<EE / 16, 256, 0, st>>>(
            delta + mo * EE, ug + mo * EE, dbc + mo * SEL,
            A_log, D_param, yh + mo * EE);

        // 6) out_b = y_b @ W_out^T  [2048, 1024], K=2048
        k_g6<<<dim3(DM / 128, LEN / 128), 512, SM_G6, st>>>(
            yh + mo * EE, wouth, out + mo * DM, EE, EE, EE, DM, nullptr, nullptr);
    }

    cudaEventRecord(evJoin, s1);
    cudaStreamWaitEvent(0, evJoin, 0);
}

// round 15
// speedup vs baseline: 1.2518x; 1.0322x over previous
#include <cuda_runtime.h>
#include <cuda_fp16.h>
#include <cstdint>

// Problem constants (ClassicMambaBlock: B=2, L=2048, Dm=1024, E=2048, N=16, R=64, K=3)
static constexpr int BSZ  = 2;
static constexpr int LEN  = 2048;
static constexpr int DM   = 1024;
static constexpr int EE   = 2048;
static constexpr int NN   = 16;
static constexpr int RR   = 64;
static constexpr int SEL  = RR + 2 * NN;   // 96
static constexpr int SELP = 128;           // padded to 128 for sel-GEMM tiling
static constexpr int MTOT = BSZ * LEN;     // 4096

// ---------------- scratch (no cudaMalloc allowed; +2 rows padding for scan prefetch) ----
__device__ float  g_xz[MTOT * 2 * EE];        // [M,4096]: cols [0,E)=xc, [E,2E)=z
__device__ float2 g_ug[(MTOT + 2) * EE];      // {u, silu(z)} per (t,e)
__device__ float  g_delta[(MTOT + 2) * EE];   // softplus(dt)
__device__ float  g_dbc[(MTOT + 2) * SEL];    // [M,96]: dt_low | B | C
// fp16 GEMM operands
__device__ __half g_xh[MTOT * DM];
__device__ __half g_winh[2 * EE * DM];
__device__ __half g_wselh[SELP * EE];         // rows 96..127 zero-padded
__device__ __half g_dtwh[EE * RR];
__device__ __half g_wouth[DM * EE];
__device__ __half g_uh[MTOT * EE];            // conv output (sel-GEMM A)
__device__ __half g_dtlh[MTOT * RR];          // dt_low (delta-GEMM A), lda=64
__device__ __half g_yh[MTOT * EE];            // scan output (out-GEMM A)

// ================= helpers =================
__device__ __forceinline__ uint32_t smem_u32(const void* p) {
    uint32_t a;
    asm("{ .reg .u64 t; cvta.to.shared.u64 t, %1; cvt.u32.u64 %0, t; }" : "=r"(a) : "l"(p));
    return a;
}
__device__ __forceinline__ void cp_async16(uint32_t dst, const void* src) {
    asm volatile("cp.async.cg.shared.global [%0], [%1], 16;" :: "r"(dst), "l"(src));
}
__device__ __forceinline__ void ldm_x4(uint32_t* r, uint32_t addr) {
    asm volatile("ldmatrix.sync.aligned.m8n8.x4.shared.b16 {%0,%1,%2,%3}, [%4];"
                 : "=r"(r[0]), "=r"(r[1]), "=r"(r[2]), "=r"(r[3]) : "r"(addr));
}
__device__ __forceinline__ void mma_f16(float* d, const uint32_t* a, const uint32_t* b) {
    asm volatile(
        "mma.sync.aligned.m16n8k16.row.col.f32.f16.f16.f32 "
        "{%0,%1,%2,%3}, {%4,%5,%6,%7}, {%8,%9}, {%0,%1,%2,%3};"
        : "+f"(d[0]), "+f"(d[1]), "+f"(d[2]), "+f"(d[3])
        : "r"(a[0]), "r"(a[1]), "r"(a[2]), "r"(a[3]), "r"(b[0]), "r"(b[1]));
}

// ---------------- fp32 -> fp16 convert: critical (x, W_in) + deferred (rest) ------------
static constexpr int C4_X    = MTOT * DM / 4;
static constexpr int C4_WIN  = 2 * EE * DM / 4;
static constexpr int C4_CRIT = C4_X + C4_WIN;
static constexpr int C4_WSEL = SEL * EE / 4;
static constexpr int C4_DTW  = EE * RR / 4;
static constexpr int C4_WOUT = DM * EE / 4;
static constexpr int C4_PAD  = (SELP - SEL) * EE / 4;
static constexpr int C4_REST = C4_WSEL + C4_DTW + C4_WOUT + C4_PAD;

__device__ __forceinline__ void cvt_store(const float4* src, __half* dst, int j) {
    float4 v = src[j];
    __half2 h01 = __floats2half2_rn(v.x, v.y);
    __half2 h23 = __floats2half2_rn(v.z, v.w);
    uint2 pk = make_uint2(*reinterpret_cast<uint32_t*>(&h01), *reinterpret_cast<uint32_t*>(&h23));
    reinterpret_cast<uint2*>(dst)[j] = pk;
}

__global__ __launch_bounds__(256)
void to_half_crit(const float4* __restrict__ x,   __half* __restrict__ xh,
                  const float4* __restrict__ win, __half* __restrict__ winh)
{
    int i = blockIdx.x * blockDim.x + threadIdx.x;
    if (i >= C4_CRIT) return;
    if (i < C4_X) cvt_store(x, xh, i);
    else          cvt_store(win, winh, i - C4_X);
}

__global__ __launch_bounds__(256)
void to_half_rest(const float4* __restrict__ wsel, __half* __restrict__ wselh,
                  const float4* __restrict__ dtw,  __half* __restrict__ dtwh,
                  const float4* __restrict__ wout, __half* __restrict__ wouth)
{
    int i = blockIdx.x * blockDim.x + threadIdx.x;
    if (i >= C4_REST) return;
    int j = i;
    if (j < C4_WSEL) { cvt_store(wsel, wselh, j); return; }
    if ((j -= C4_WSEL) < C4_DTW) { cvt_store(dtw, dtwh, j); return; }
    if ((j -= C4_DTW) < C4_WOUT) { cvt_store(wout, wouth, j); return; }
    j -= C4_WOUT;   // zero pad rows 96..127 of wselh
    reinterpret_cast<uint2*>(wselh + SEL * EE)[j] = make_uint2(0u, 0u);
}

// ================= fp16 tensor GEMM: C[M,N] = A[M,K] @ B[N,K]^T, fp32 accum =============
// R6/R10 mainloop. BK = 64 fp16 (128B rows). smem: 16B unit at (c*ROWS + (r ^ c))*16,
// c = k/8. ldmatrix.x4 fragments; STAGES-deep cp.async pipeline.
// EPI: 0 = none; 1 = softplus(x+bias); 2 = dual write (fp32 cols<SEL into C with ldc,
// fp16 cols<RR into Ch with lda RR).
template<int BM, int BN, int WM, int WN, int STAGES, int EPI>
__global__ __launch_bounds__((BM / WM) * (BN / WN) * 32)
void mma_gemm(const __half* __restrict__ A, const __half* __restrict__ Bw,
              float* __restrict__ C, int K, int lda, int ldb, int ldc,
              const float* __restrict__ bias, __half* __restrict__ Ch)
{
    constexpr int WARPS_M = BM / WM;
    constexpr int WARPS_N = BN / WN;
    constexpr int THREADS = WARPS_M * WARPS_N * 32;
    constexpr int MT = WM / 16;
    constexpr int NT = WN / 8;
    constexpr int STAGE_B = (BM + BN) * 128;
    static_assert(NT % 2 == 0, "NT even");

    extern __shared__ char smem[];
    const uint32_t smem_b = smem_u32(smem);

    const int tid  = threadIdx.x;
    const int lane = tid & 31, wid = tid >> 5;
    const int wm = wid % WARPS_M, wn = wid / WARPS_M;
    const int qr = lane >> 2, kin = lane & 3;
    const int m0 = blockIdx.y * BM, n0 = blockIdx.x * BN;
    const int lrow = lane & 15, lcof = lane >> 4;

    float acc[MT][NT][4];
#pragma unroll
    for (int i = 0; i < MT; i++)
#pragma unroll
        for (int j = 0; j < NT; j++)
#pragma unroll
            for (int q = 0; q < 4; q++) acc[i][j][q] = 0.f;

    auto load_chunk = [&](int ck, int slot) {
        const int kt = ck * 64;
        const uint32_t ab = smem_b + slot * STAGE_B;
        const uint32_t bb = ab + BM * 128;
#pragma unroll
        for (int it = 0; it < BM * 8 / THREADS; it++) {
            int idx = tid + it * THREADS;
            int r = idx >> 3, c = idx & 7;
            cp_async16(ab + (uint32_t)(c * BM + (r ^ c)) * 16,
                       A + (size_t)(m0 + r) * lda + kt + c * 8);
        }
#pragma unroll
        for (int it = 0; it < BN * 8 / THREADS; it++) {
            int idx = tid + it * THREADS;
            int r = idx >> 3, c = idx & 7;
            cp_async16(bb + (uint32_t)(c * BN + (r ^ c)) * 16,
                       Bw + (size_t)(n0 + r) * ldb + kt + c * 8);
        }
        asm volatile("cp.async.commit_group;" ::: "memory");
    };

    const int nch = K / 64;
#pragma unroll
    for (int s = 0; s < STAGES - 1; s++)
        if (s < nch) load_chunk(s, s);

    for (int i = 0; i < nch; i++) {
        int w = nch - 1 - i;
        if (w > STAGES - 2) w = STAGES - 2;
        if      (w <= 0) asm volatile("cp.async.wait_group 0;" ::: "memory");
        else if (w == 1) asm volatile("cp.async.wait_group 1;" ::: "memory");
        else if (w == 2) asm volatile("cp.async.wait_group 2;" ::: "memory");
        else if (w == 3) asm volatile("cp.async.wait_group 3;" ::: "memory");
        else             asm volatile("cp.async.wait_group 4;" ::: "memory");
        __syncthreads();

        const uint32_t sa = smem_b + (i % STAGES) * STAGE_B;
        const uint32_t sb = sa + BM * 128;
#pragma unroll
        for (int ks = 0; ks < 4; ks++) {
            const int c = 2 * ks + lcof;
            uint32_t af[MT][4], bf[NT][2];
#pragma unroll
            for (int t = 0; t < MT; t++) {
                const int row = wm * WM + t * 16 + lrow;
                ldm_x4(af[t], sa + (uint32_t)(c * BM + (row ^ c)) * 16);
            }
#pragma unroll
            for (int p = 0; p < NT / 2; p++) {
                const int row = wn * WN + p * 16 + lrow;
                uint32_t r4[4];
                ldm_x4(r4, sb + (uint32_t)(c * BN + (row ^ c)) * 16);
                bf[2 * p][0] = r4[0]; bf[2 * p + 1][0] = r4[1];
                bf[2 * p][1] = r4[2]; bf[2 * p + 1][1] = r4[3];
            }
#pragma unroll
            for (int t = 0; t < MT; t++)
#pragma unroll
                for (int j = 0; j < NT; j++)
                    mma_f16(acc[t][j], af[t], bf[j]);
        }
        __syncthreads();

        const int pre = i + STAGES - 1;
        if (pre < nch) load_chunk(pre, pre % STAGES);
    }

    // ---------------- epilogue ----------------
#pragma unroll
    for (int t = 0; t < MT; t++) {
#pragma unroll
        for (int j = 0; j < NT; j++) {
            const int row = m0 + wm * WM + t * 16 + qr;
            const int col = n0 + wn * WN + j * 8 + kin * 2;
            float v0 = acc[t][j][0], v1 = acc[t][j][1];
            float v2 = acc[t][j][2], v3 = acc[t][j][3];
            if (EPI == 1) {
                const float b0 = bias[col], b1 = bias[col + 1];
                float x0 = v0 + b0, x1 = v1 + b1, x2 = v2 + b0, x3 = v3 + b1;
                v0 = (x0 > 20.f) ? x0 : log1pf(__expf(x0));
                v1 = (x1 > 20.f) ? x1 : log1pf(__expf(x1));
                v2 = (x2 > 20.f) ? x2 : log1pf(__expf(x2));
                v3 = (x3 > 20.f) ? x3 : log1pf(__expf(x3));
            }
            if (EPI == 2) {
                if (col < SEL) {
                    *reinterpret_cast<float2*>(C + (size_t)row * ldc + col)       = make_float2(v0, v1);
                    *reinterpret_cast<float2*>(C + (size_t)(row + 8) * ldc + col) = make_float2(v2, v3);
                }
                if (col < RR) {
                    *reinterpret_cast<__half2*>(Ch + (size_t)row * RR + col)
                        = __floats2half2_rn(v0, v1);
                    *reinterpret_cast<__half2*>(Ch + (size_t)(row + 8) * RR + col)
                        = __floats2half2_rn(v2, v3);
                }
            } else {
                *reinterpret_cast<float2*>(C + (size_t)row * ldc + col)       = make_float2(v0, v1);
                *reinterpret_cast<float2*>(C + (size_t)(row + 8) * ldc + col) = make_float2(v2, v3);
            }
        }
    }
}

// ---------------- causal depthwise conv1d (K=3) + bias + SiLU; also silu(z) -------------
__global__ __launch_bounds__(256)
void conv_silu_kernel(const float* __restrict__ xz_b,
                      const float* __restrict__ cw,
                      const float* __restrict__ cb,
                      float2* __restrict__ ug_b,
                      __half* __restrict__ uh_b)
{
    int idx = blockIdx.x * blockDim.x + threadIdx.x;   // over LEN*E
    int e = idx % EE;
    int t = idx / EE;

    float acc = cb[e];
    float w0 = cw[e * 3 + 0], w1 = cw[e * 3 + 1], w2 = cw[e * 3 + 2];
    if (t >= 2) acc = fmaf(w0, xz_b[(size_t)(t - 2) * (2 * EE) + e], acc);
    if (t >= 1) acc = fmaf(w1, xz_b[(size_t)(t - 1) * (2 * EE) + e], acc);
    acc = fmaf(w2, xz_b[(size_t)t * (2 * EE) + e], acc);
    float s = acc / (1.f + __expf(-acc));              // silu(conv)
    float zv = xz_b[(size_t)t * (2 * EE) + EE + e];    // z
    float gz = zv / (1.f + __expf(-zv));               // silu(z)
    ug_b[idx] = make_float2(s, gz);
    uh_b[idx] = __float2half_rn(s);
}

// ---------------- selective scan (per batch): software-pipelined reduction --------------
__global__ __launch_bounds__(256)
void scan_kernel(const float* __restrict__ delta_b,
                 const float2* __restrict__ ug_b,
                 const float* __restrict__ dbc_b,
                 const float* __restrict__ A_log,
                 const float* __restrict__ D_param,
                 __half* __restrict__ yh_b)
{
    const int e    = blockIdx.x * (blockDim.x >> 4) + (threadIdx.x >> 4); // [0, E)
    const int lane = threadIdx.x & 31;
    const int n    = threadIdx.x & 15;

    const float An = -__expf(A_log[e * NN + n]);
    const float Dp = D_param[e];

    const float*  dptr = delta_b + e;
    const float2* gptr = ug_b + e;
    const float*  vptr = dbc_b + RR + lane;   // B|C packed: one 32-lane LDG
    __half*       yptr = yh_b + e;

    float h = 0.f;
    float  d0 = dptr[0], d1 = dptr[EE];
    float2 g0 = gptr[0], g1 = gptr[EE];
    float  v0 = vptr[0], v1 = vptr[SEL];

    float r1 = 0.f, r2 = 0.f, r3 = 0.f;
    float2 gH0 = make_float2(0.f, 0.f), gH1 = gH0, gH2 = gH0;

    for (int t = 0; t < LEN; t++) {
        float  d2 = dptr[(size_t)(t + 2) * EE];
        float2 g2 = gptr[(size_t)(t + 2) * EE];
        float  v2 = vptr[(size_t)(t + 2) * SEL];

        const float Bc = __shfl_sync(0xffffffffu, v0, n);
        const float Cc = __shfl_sync(0xffffffffu, v0, n + 16);
        float dA = __expf(d0 * An);
        h = fmaf(dA, h, d0 * g0.x * Bc);
        float p = h * Cc;

        float s4 = r3 + __shfl_xor_sync(0xffffffffu, r3, 8);
        float n3 = r2 + __shfl_xor_sync(0xffffffffu, r2, 4);
        float n2 = r1 + __shfl_xor_sync(0xffffffffu, r1, 2);
        float n1 = p  + __shfl_xor_sync(0xffffffffu, p,  1);
        if (n == 0 && t >= 3)
            yptr[(size_t)(t - 3) * EE] = __float2half_rn((s4 + gH2.x * Dp) * gH2.y);
        r3 = n3; r2 = n2; r1 = n1;
        gH2 = gH1; gH1 = gH0; gH0 = g0;

        d0 = d1; g0 = g1; v0 = v1;
        d1 = d2; g1 = g2; v1 = v2;
    }

#pragma unroll
    for (int k = 0; k < 3; k++) {
        float s4 = r3 + __shfl_xor_sync(0xffffffffu, r3, 8);
        float n3 = r2 + __shfl_xor_sync(0xffffffffu, r2, 4);
        float n2 = r1 + __shfl_xor_sync(0xffffffffu, r1, 2);
        if (n == 0)
            yptr[(size_t)(LEN - 3 + k) * EE] = __float2half_rn((s4 + gH2.x * Dp) * gH2.y);
        r3 = n3; r2 = n2;
        gH2 = gH1; gH1 = gH0;
    }
}

// ---------------- launch: batch-pipelined G1 + chains on two streams ---------------------
extern "C" void kernel_launch(void* const* d_in, const int* in_sizes, int n_in,
                              void* d_out, int out_size)
{
    const float* x       = (const float*)d_in[0];
    const float* W_in    = (const float*)d_in[1];
    const float* conv_w  = (const float*)d_in[2];
    const float* conv_b  = (const float*)d_in[3];
    const float* W_sel   = (const float*)d_in[4];
    const float* dt_w    = (const float*)d_in[5];
    const float* dt_b    = (const float*)d_in[6];
    const float* A_log   = (const float*)d_in[7];
    const float* D_param = (const float*)d_in[8];
    const float* W_out   = (const float*)d_in[9];
    float* out = (float*)d_out;

    float *xz, *delta, *dbc;
    float2* ug;
    __half *xh, *winh, *wselh, *dtwh, *wouth, *uh, *dtlh, *yh;
    cudaGetSymbolAddress((void**)&xz,    g_xz);
    cudaGetSymbolAddress((void**)&ug,    g_ug);
    cudaGetSymbolAddress((void**)&delta, g_delta);
    cudaGetSymbolAddress((void**)&dbc,   g_dbc);
    cudaGetSymbolAddress((void**)&xh,    g_xh);
    cudaGetSymbolAddress((void**)&winh,  g_winh);
    cudaGetSymbolAddress((void**)&wselh, g_wselh);
    cudaGetSymbolAddress((void**)&dtwh,  g_dtwh);
    cudaGetSymbolAddress((void**)&wouth, g_wouth);
    cudaGetSymbolAddress((void**)&uh,    g_uh);
    cudaGetSymbolAddress((void**)&dtlh,  g_dtlh);
    cudaGetSymbolAddress((void**)&yh,    g_yh);

    // kernel variants: big tile (256x128) for G1 halves AND G6
    auto* k_big = mma_gemm<256, 128, 64, 32, 4, 0>;   // 512 thr, 16 warps
    auto* k_dlt = mma_gemm<128, 128, 32, 32, 2, 1>;   // K=64 -> 1 chunk
    auto* k_sel = mma_gemm< 32, 128, 32, 16, 6, 2>;   // 256 thr, 6 stages, dual-write

    constexpr int SM_BIG = 4 * (256 + 128) * 128;  // 196608
    constexpr int SM_DLT = 2 * (128 + 128) * 128;  // 65536
    constexpr int SM_SEL = 6 * ( 32 + 128) * 128;  // 122880
    cudaFuncSetAttribute((const void*)k_big, cudaFuncAttributeMaxDynamicSharedMemorySize, SM_BIG);
    cudaFuncSetAttribute((const void*)k_dlt, cudaFuncAttributeMaxDynamicSharedMemorySize, SM_DLT);
    cudaFuncSetAttribute((const void*)k_sel, cudaFuncAttributeMaxDynamicSharedMemorySize, SM_SEL);

    // Fork/join plumbing (host objects only; never destroyed — capture-safe, proven R9-R14).
    cudaStream_t s1;
    cudaStreamCreateWithFlags(&s1, cudaStreamNonBlocking);
    cudaEvent_t evFork0, evG1a, evRest, evJoin;
    cudaEventCreateWithFlags(&evFork0, cudaEventDisableTiming);
    cudaEventCreateWithFlags(&evG1a,   cudaEventDisableTiming);
    cudaEventCreateWithFlags(&evRest,  cudaEventDisableTiming);
    cudaEventCreateWithFlags(&evJoin,  cudaEventDisableTiming);

    // 0a) critical convert (x, W_in) on s0
    to_half_crit<<<(C4_CRIT + 255) / 256, 256>>>(
        (const float4*)x, xh, (const float4*)W_in, winh);

    // Fork s1 from s0 (after s0 has captured work)
    cudaEventRecord(evFork0, 0);
    cudaStreamWaitEvent(s1, evFork0, 0);

    // 0b) deferred weight convert on s1 (overlaps G1a on s0)
    to_half_rest<<<(C4_REST + 255) / 256, 256, 0, s1>>>(
        (const float4*)W_sel, wselh, (const float4*)dt_w, dtwh,
        (const float4*)W_out, wouth);
    cudaEventRecord(evRest, s1);

    // 1a) G1 batch 0 on s0: xz[0:2048] = x[0:2048] @ W_in^T  (grid 32x8 = 256 CTAs)
    k_big<<<dim3((2 * EE) / 128, LEN / 256), 512, SM_BIG>>>(
        xh, winh, xz, DM, DM, DM, 2 * EE, nullptr, nullptr);
    cudaEventRecord(evG1a, 0);

    // 1b) G1 batch 1 on s1 (starts after G1a; runs under chain-0's non-MAC work)
    cudaStreamWaitEvent(s1, evG1a, 0);
    k_big<<<dim3((2 * EE) / 128, LEN / 256), 512, SM_BIG, s1>>>(
        xh + (size_t)LEN * DM, winh, xz + (size_t)LEN * 2 * EE,
        DM, DM, DM, 2 * EE, nullptr, nullptr);

    // s0's chain needs the deferred weights converted on s1.
    cudaStreamWaitEvent(0, evRest, 0);

    for (int b = 0; b < BSZ; b++) {
        cudaStream_t st = (b == 0) ? (cudaStream_t)0 : s1;
        const size_t mo = (size_t)b * LEN;

        // 2) conv + silu + silu(z)
        conv_silu_kernel<<<(LEN * EE) / 256, 256, 0, st>>>(
            xz + mo * 2 * EE, conv_w, conv_b, ug + mo * EE, uh + mo * EE);

        // 3) dbc_b = u_b @ W_sel^T  [2048, 96(pad128)], K=2048  (+ fp16 dt_low)
        k_sel<<<dim3(1, LEN / 32), 256, SM_SEL, st>>>(
            uh + mo * EE, wselh, dbc + mo * SEL, EE, EE, EE, SEL, nullptr,
            dtlh + mo * RR);

        // 4) delta_b = softplus(dt_low_b @ dt_w^T + dt_b)  [2048, 2048], K=64
        k_dlt<<<dim3(EE / 128, LEN / 128), 512, SM_DLT, st>>>(
            dtlh + mo * RR, dtwh, delta + mo * EE, RR, RR, RR, EE, dt_b, nullptr);

        // 5) selective scan (pipelined reduction) -> y_b (fp16)
        scan_kernel<<<EE / 16, 256, 0, st>>>(
            delta + mo * EE, ug + mo * EE, dbc + mo * SEL,
            A_log, D_param, yh + mo * EE);

        // 6) out_b = y_b @ W_out^T  [2048, 1024], K=2048  (256x128 tiles, 64 CTAs)
        k_big<<<dim3(DM / 128, LEN / 256), 512, SM_BIG, st>>>(
            yh + mo * EE, wouth, out + mo * DM, EE, EE, EE, DM, nullptr, nullptr);
    }

    cudaEventRecord(evJoin, s1);
    cudaStreamWaitEvent(0, evJoin, 0);
}